// round 2
// baseline (speedup 1.0000x reference)
#include <cuda_runtime.h>
#include <cstdint>

#define NCTA 128
#define NTHR 256
#define Bb   1024
#define Tt   512
#define Hh   512
#define Pp   48
#define STEPS (Tt + Pp)
#define BC   512          // batches per CTA
#define RC   32           // gate rows per CTA (8 units x 4 gates)
#define KC   16           // k rows per staged chunk
#define NCHUNK (Hh / KC)  // 32

// ---------------- device scratch (no runtime allocation allowed) ----------
__device__ float             g_h[2][Hh * Bb];  // ping-pong h, [unit][batch]
__device__ float             g_xT[Tt * Bb];    // transposed input x: [t][b]
__device__ unsigned          g_cnt;
__device__ volatile unsigned g_gen;

__device__ __forceinline__ void grid_bar() {
    __syncthreads();
    if (threadIdx.x == 0) {
        __threadfence();
        unsigned gen = g_gen;
        unsigned t = atomicAdd(&g_cnt, 1u);
        if (t == NCTA - 1) {
            g_cnt = 0;
            __threadfence();
            g_gen = gen + 1;
        } else {
            while (g_gen == gen) { __nanosleep(64); }
        }
        __threadfence();
    }
    __syncthreads();
}

__device__ __forceinline__ float sigm(float x) {
    return __fdividef(1.f, 1.f + __expf(-x));
}
__device__ __forceinline__ float tanhx(float x) {
    float e = __expf(-2.f * fabsf(x));
    float t = __fdividef(1.f - e, 1.f + e);
    return copysignf(t, x);
}
__device__ __forceinline__ float2 upk(unsigned long long v) {
    float2 r;
    asm("mov.b64 {%0,%1}, %2;" : "=f"(r.x), "=f"(r.y) : "l"(v));
    return r;
}
__device__ __forceinline__ void cpa16(unsigned dst, const float* src) {
    asm volatile("cp.async.cg.shared.global [%0], [%1], 16;" :: "r"(dst), "l"(src));
}

// SMEM layout (bytes):
//   w2  : [Hh][RC] float2 dup pairs   131072
//   hsm : 2 x [KC][BC] float           65536
//   xsm : [BC] float                    2048
//   wfc : [Hh] float                    2048
//   bsm : [RC] float                     128
//   wis : [RC] float                     128
#define SMEM_BYTES (131072 + 65536 + 2048 + 2048 + 128 + 128)

extern "C" __global__ void __launch_bounds__(NTHR, 1)
lstm_pers(const float* __restrict__ x,
          const float* __restrict__ w_ih,
          const float* __restrict__ w_hh,
          const float* __restrict__ b_ih,
          const float* __restrict__ b_hh,
          const float* __restrict__ w_fc,
          const float* __restrict__ b_fc,
          float* __restrict__ dout)
{
    extern __shared__ __align__(16) char smem_raw[];
    float2* w2  = reinterpret_cast<float2*>(smem_raw);
    float*  hsm = reinterpret_cast<float*>(smem_raw + 131072);
    float*  xsm = hsm + 2 * KC * BC;
    float*  wfc = xsm + BC;
    float*  bsm = wfc + Hh;
    float*  wis = bsm + RC;

    const int tid = threadIdx.x;
    const int ci  = blockIdx.x;
    const int u0  = (ci >> 1) * 8;     // first owned h-unit
    const int b0  = (ci & 1) * BC;     // first owned batch
    const int bg  = tid & 63;          // batch group
    const int rg  = tid >> 6;          // row group (8 rows = 2 units x 4 gates)

    // ---------------- prologue ----------------
    {   // zero h ping buffer 0
        const int per = (Hh * Bb) / NCTA;  // 4096
        float* p = &g_h[0][ci * per];
        for (int i = tid; i < per; i += NTHR) p[i] = 0.f;
    }
    {   // transpose x[b][t] -> g_xT[t][b]
        const int per  = (Bb * Tt) / NCTA; // 4096
        const int base = ci * per;
        for (int i = tid; i < per; i += NTHR) {
            int idx = base + i;
            g_xT[(idx & (Tt - 1)) * Bb + (idx >> 9)] = x[idx];
        }
    }
    {   // owned weight rows -> SMEM, duplicated (w,w)
        int r    = tid >> 3;           // local row 0..31
        int l8   = tid & 7;
        int gate = r & 3, uu = r >> 2;
        int row  = gate * Hh + u0 + uu;
        for (int k = l8; k < Hh; k += 8) {
            float v = w_hh[row * Hh + k];
            w2[k * RC + r] = make_float2(v, v);
        }
        if (l8 == 0) {
            bsm[r] = b_ih[row] + b_hh[row];
            wis[r] = w_ih[row];        // IN == 1
        }
    }
    for (int k = tid; k < Hh; k += NTHR) wfc[k] = w_fc[k];
    const float bfc = b_fc[0];

    float creg[2][2][2][2];            // [quad][pair][unit][lane]
    #pragma unroll
    for (int q = 0; q < 2; q++)
        #pragma unroll
        for (int e = 0; e < 2; e++)
            #pragma unroll
            for (int ul = 0; ul < 2; ul++) {
                creg[q][e][ul][0] = 0.f; creg[q][e][ul][1] = 0.f;
            }

    const unsigned hsm_sa = (unsigned)__cvta_generic_to_shared(hsm);
    const int srow = tid >> 7;         // staging row parity
    const int scol = (tid & 127) * 4;  // staging column (floats)

    grid_bar();

    // ---------------- 560 sequential cell steps ----------------
    for (int t = 0; t < STEPS; ++t) {
        const float* __restrict__ hsrc = g_h[t & 1];
        float* __restrict__       hdst = g_h[(t + 1) & 1];
        const bool dec = (t >= Tt);

        if (!dec)   // encoder input: scalar x per batch
            *(float2*)&xsm[tid * 2] =
                *(const float2*)&g_xT[t * Bb + b0 + tid * 2];

        unsigned long long acc[2][2][8];
        #pragma unroll
        for (int q = 0; q < 2; q++)
            #pragma unroll
            for (int e = 0; e < 2; e++)
                #pragma unroll
                for (int j = 0; j < 8; j++) acc[q][e][j] = 0ull;

        float oax = 0.f, oay = 0.f;    // decoder fc-dot partials

        // stage chunk 0
        {
            const float* src = hsrc + srow * Bb + b0 + scol;
            unsigned dst = hsm_sa + (unsigned)((srow * BC + scol) * 4);
            #pragma unroll
            for (int j = 0; j < 8; ++j)
                cpa16(dst + (unsigned)(j * 2 * BC * 4), src + j * 2 * Bb);
            asm volatile("cp.async.commit_group;");
        }

        for (int c = 0; c < NCHUNK; ++c) {
            if (c + 1 < NCHUNK) {
                const float* src = hsrc + ((c + 1) * KC + srow) * Bb + b0 + scol;
                unsigned dst = hsm_sa +
                    (unsigned)(((((c + 1) & 1) * KC + srow) * BC + scol) * 4);
                #pragma unroll
                for (int j = 0; j < 8; ++j)
                    cpa16(dst + (unsigned)(j * 2 * BC * 4), src + j * 2 * Bb);
                asm volatile("cp.async.commit_group;");
                asm volatile("cp.async.wait_group 1;");
            } else {
                asm volatile("cp.async.wait_group 0;");
            }
            __syncthreads();

            const float* hb = hsm + (c & 1) * KC * BC;

            if (dec) {  // fc(h) dot while the chunk is resident
                #pragma unroll
                for (int kk = 0; kk < KC; ++kk) {
                    float2 hv = *(const float2*)&hb[kk * BC + tid * 2];
                    float  wv = wfc[c * KC + kk];
                    oax = fmaf(hv.x, wv, oax);
                    oay = fmaf(hv.y, wv, oay);
                }
            }

            // GEMM core: packed fp32x2 FMA, batch-paired accumulators
            #pragma unroll
            for (int kk = 0; kk < KC; ++kk) {
                const ulonglong2* wp =
                    (const ulonglong2*)&w2[(c * KC + kk) * RC + rg * 8];
                ulonglong2 wA = wp[0], wB = wp[1], wC = wp[2], wD = wp[3];
                ulonglong2 a0 = *(const ulonglong2*)&hb[kk * BC + bg * 4];
                ulonglong2 a1 = *(const ulonglong2*)&hb[kk * BC + 256 + bg * 4];
                unsigned long long av[2][2] = {{a0.x, a0.y}, {a1.x, a1.y}};
                unsigned long long wv[8] = {wA.x, wA.y, wB.x, wB.y,
                                            wC.x, wC.y, wD.x, wD.y};
                #pragma unroll
                for (int q = 0; q < 2; ++q)
                    #pragma unroll
                    for (int e = 0; e < 2; ++e)
                        #pragma unroll
                        for (int j = 0; j < 8; ++j)
                            asm("fma.rn.f32x2 %0, %1, %2, %0;"
                                : "+l"(acc[q][e][j])
                                : "l"(av[q][e]), "l"(wv[j]));
            }
            __syncthreads();
        }

        if (dec) {  // finalize fc: prediction + next-step input
            float ox = oax + bfc, oy = oay + bfc;
            int b2 = tid * 2;
            xsm[b2] = ox; xsm[b2 + 1] = oy;
            int p = t - Tt;
            dout[(b0 + b2) * Pp + p]     = ox;
            dout[(b0 + b2 + 1) * Pp + p] = oy;
            __syncthreads();
        }

        // ---- epilogue: gates, c/h update, store h ----
        #pragma unroll
        for (int q = 0; q < 2; ++q) {
            #pragma unroll
            for (int e = 0; e < 2; ++e) {
                int bb = q * 256 + bg * 4 + e * 2;
                float xt0 = xsm[bb], xt1 = xsm[bb + 1];
                #pragma unroll
                for (int ul = 0; ul < 2; ++ul) {
                    float2 gi = upk(acc[q][e][ul * 4 + 0]);
                    float2 gf = upk(acc[q][e][ul * 4 + 1]);
                    float2 gg = upk(acc[q][e][ul * 4 + 2]);
                    float2 go = upk(acc[q][e][ul * 4 + 3]);
                    int r = rg * 8 + ul * 4;
                    float bi = bsm[r], bf = bsm[r + 1];
                    float bgv = bsm[r + 2], bo = bsm[r + 3];
                    float wi = wis[r], wf = wis[r + 1];
                    float wg = wis[r + 2], wo = wis[r + 3];
                    gi.x += bi + xt0 * wi;   gi.y += bi + xt1 * wi;
                    gf.x += bf + xt0 * wf;   gf.y += bf + xt1 * wf;
                    gg.x += bgv + xt0 * wg;  gg.y += bgv + xt1 * wg;
                    go.x += bo + xt0 * wo;   go.y += bo + xt1 * wo;

                    float c0 = creg[q][e][ul][0];
                    float c1 = creg[q][e][ul][1];
                    c0 = sigm(gf.x) * c0 + sigm(gi.x) * tanhx(gg.x);
                    c1 = sigm(gf.y) * c1 + sigm(gi.y) * tanhx(gg.y);
                    creg[q][e][ul][0] = c0;
                    creg[q][e][ul][1] = c1;
                    float h0 = sigm(go.x) * tanhx(c0);
                    float h1 = sigm(go.y) * tanhx(c1);

                    int gu = u0 + rg * 2 + ul;
                    __stcg((float2*)&hdst[gu * Bb + b0 + bb],
                           make_float2(h0, h1));
                }
            }
        }

        grid_bar();
    }
}

extern "C" void kernel_launch(void* const* d_in, const int* in_sizes, int n_in,
                              void* d_out, int out_size) {
    (void)in_sizes; (void)n_in; (void)out_size;
    cudaFuncSetAttribute(lstm_pers,
                         cudaFuncAttributeMaxDynamicSharedMemorySize,
                         SMEM_BYTES);
    lstm_pers<<<NCTA, NTHR, SMEM_BYTES>>>(
        (const float*)d_in[0],   // x
        (const float*)d_in[1],   // w_ih
        (const float*)d_in[2],   // w_hh
        (const float*)d_in[3],   // b_ih
        (const float*)d_in[4],   // b_hh
        (const float*)d_in[5],   // w_fc
        (const float*)d_in[6],   // b_fc
        (float*)d_out);
}

// round 3
// speedup vs baseline: 1.0004x; 1.0004x over previous
#include <cuda_runtime.h>
#include <cstdint>

#define NCTA 128
#define NTHR 256
#define Bb   1024
#define Tt   512
#define Hh   512
#define Pp   48
#define STEPS (Tt + Pp)
#define BC   512          // batches per CTA
#define RC   32           // gate rows per CTA (8 units x 4 gates)
#define KC   16           // k rows per staged chunk
#define NCHUNK (Hh / KC)  // 32

// ---------------- device scratch (no runtime allocation allowed) ----------
__device__ float             g_h[2][Hh * Bb];  // ping-pong h, [unit][batch]
__device__ float             g_xT[Tt * Bb];    // transposed input x: [t][b]
__device__ unsigned          g_cnt;
__device__ volatile unsigned g_gen;

__device__ __forceinline__ void grid_bar() {
    __syncthreads();
    if (threadIdx.x == 0) {
        __threadfence();
        unsigned gen = g_gen;
        unsigned t = atomicAdd(&g_cnt, 1u);
        if (t == NCTA - 1) {
            g_cnt = 0;
            __threadfence();
            g_gen = gen + 1;
        } else {
            while (g_gen == gen) { __nanosleep(64); }
        }
        __threadfence();
    }
    __syncthreads();
}

__device__ __forceinline__ float sigm(float x) {
    return __fdividef(1.f, 1.f + __expf(-x));
}
__device__ __forceinline__ float tanhx(float x) {
    float e = __expf(-2.f * fabsf(x));
    float t = __fdividef(1.f - e, 1.f + e);
    return copysignf(t, x);
}
__device__ __forceinline__ float2 upk(unsigned long long v) {
    float2 r;
    asm("mov.b64 {%0,%1}, %2;" : "=f"(r.x), "=f"(r.y) : "l"(v));
    return r;
}
__device__ __forceinline__ void cpa16(unsigned dst, const float* src) {
    asm volatile("cp.async.cg.shared.global [%0], [%1], 16;" :: "r"(dst), "l"(src));
}

// SMEM layout (bytes):
//   w2  : [Hh][RC] float2 dup pairs   131072
//   hsm : 2 x [KC][BC] float           65536
//   xsm : [BC] float                    2048
//   wfc : [Hh] float                    2048
//   bsm : [RC] float                     128
//   wis : [RC] float                     128
#define SMEM_BYTES (131072 + 65536 + 2048 + 2048 + 128 + 128)

extern "C" __global__ void __launch_bounds__(NTHR, 1)
lstm_pers(const float* __restrict__ x,
          const float* __restrict__ w_ih,
          const float* __restrict__ w_hh,
          const float* __restrict__ b_ih,
          const float* __restrict__ b_hh,
          const float* __restrict__ w_fc,
          const float* __restrict__ b_fc,
          float* __restrict__ dout)
{
    extern __shared__ __align__(16) char smem_raw[];
    float2* w2  = reinterpret_cast<float2*>(smem_raw);
    float*  hsm = reinterpret_cast<float*>(smem_raw + 131072);
    float*  xsm = hsm + 2 * KC * BC;
    float*  wfc = xsm + BC;
    float*  bsm = wfc + Hh;
    float*  wis = bsm + RC;

    const int tid = threadIdx.x;
    const int ci  = blockIdx.x;
    const int u0  = (ci >> 1) * 8;     // first owned h-unit
    const int b0  = (ci & 1) * BC;     // first owned batch
    const int bg  = tid & 63;          // batch group
    const int rg  = tid >> 6;          // row group (8 rows = 2 units x 4 gates)

    // ---------------- prologue ----------------
    {   // zero h ping buffer 0
        const int per = (Hh * Bb) / NCTA;  // 4096
        float* p = &g_h[0][ci * per];
        for (int i = tid; i < per; i += NTHR) p[i] = 0.f;
    }
    {   // transpose x[b][t] -> g_xT[t][b]
        const int per  = (Bb * Tt) / NCTA; // 4096
        const int base = ci * per;
        for (int i = tid; i < per; i += NTHR) {
            int idx = base + i;
            g_xT[(idx & (Tt - 1)) * Bb + (idx >> 9)] = x[idx];
        }
    }
    {   // owned weight rows -> SMEM, duplicated (w,w)
        int r    = tid >> 3;           // local row 0..31
        int l8   = tid & 7;
        int gate = r & 3, uu = r >> 2;
        int row  = gate * Hh + u0 + uu;
        for (int k = l8; k < Hh; k += 8) {
            float v = w_hh[row * Hh + k];
            w2[k * RC + r] = make_float2(v, v);
        }
        if (l8 == 0) {
            bsm[r] = b_ih[row] + b_hh[row];
            wis[r] = w_ih[row];        // IN == 1
        }
    }
    for (int k = tid; k < Hh; k += NTHR) wfc[k] = w_fc[k];
    const float bfc = b_fc[0];

    float creg[2][2][2][2];            // [quad][pair][unit][lane]
    #pragma unroll
    for (int q = 0; q < 2; q++)
        #pragma unroll
        for (int e = 0; e < 2; e++)
            #pragma unroll
            for (int ul = 0; ul < 2; ul++) {
                creg[q][e][ul][0] = 0.f; creg[q][e][ul][1] = 0.f;
            }

    const unsigned hsm_sa = (unsigned)__cvta_generic_to_shared(hsm);
    const int srow = tid >> 7;         // staging row parity
    const int scol = (tid & 127) * 4;  // staging column (floats)

    grid_bar();

    // ---------------- 560 sequential cell steps ----------------
    for (int t = 0; t < STEPS; ++t) {
        const float* __restrict__ hsrc = g_h[t & 1];
        float* __restrict__       hdst = g_h[(t + 1) & 1];
        const bool dec = (t >= Tt);

        if (!dec)   // encoder input: scalar x per batch
            *(float2*)&xsm[tid * 2] =
                *(const float2*)&g_xT[t * Bb + b0 + tid * 2];

        unsigned long long acc[2][2][8];
        #pragma unroll
        for (int q = 0; q < 2; q++)
            #pragma unroll
            for (int e = 0; e < 2; e++)
                #pragma unroll
                for (int j = 0; j < 8; j++) acc[q][e][j] = 0ull;

        float oax = 0.f, oay = 0.f;    // decoder fc-dot partials

        // stage chunk 0
        {
            const float* src = hsrc + srow * Bb + b0 + scol;
            unsigned dst = hsm_sa + (unsigned)((srow * BC + scol) * 4);
            #pragma unroll
            for (int j = 0; j < 8; ++j)
                cpa16(dst + (unsigned)(j * 2 * BC * 4), src + j * 2 * Bb);
            asm volatile("cp.async.commit_group;");
        }

        for (int c = 0; c < NCHUNK; ++c) {
            if (c + 1 < NCHUNK) {
                const float* src = hsrc + ((c + 1) * KC + srow) * Bb + b0 + scol;
                unsigned dst = hsm_sa +
                    (unsigned)(((((c + 1) & 1) * KC + srow) * BC + scol) * 4);
                #pragma unroll
                for (int j = 0; j < 8; ++j)
                    cpa16(dst + (unsigned)(j * 2 * BC * 4), src + j * 2 * Bb);
                asm volatile("cp.async.commit_group;");
                asm volatile("cp.async.wait_group 1;");
            } else {
                asm volatile("cp.async.wait_group 0;");
            }
            __syncthreads();

            const float* hb = hsm + (c & 1) * KC * BC;

            if (dec) {  // fc(h) dot while the chunk is resident
                #pragma unroll
                for (int kk = 0; kk < KC; ++kk) {
                    float2 hv = *(const float2*)&hb[kk * BC + tid * 2];
                    float  wv = wfc[c * KC + kk];
                    oax = fmaf(hv.x, wv, oax);
                    oay = fmaf(hv.y, wv, oay);
                }
            }

            // GEMM core: packed fp32x2 FMA, batch-paired accumulators
            #pragma unroll
            for (int kk = 0; kk < KC; ++kk) {
                const ulonglong2* wp =
                    (const ulonglong2*)&w2[(c * KC + kk) * RC + rg * 8];
                ulonglong2 wA = wp[0], wB = wp[1], wC = wp[2], wD = wp[3];
                ulonglong2 a0 = *(const ulonglong2*)&hb[kk * BC + bg * 4];
                ulonglong2 a1 = *(const ulonglong2*)&hb[kk * BC + 256 + bg * 4];
                unsigned long long av[2][2] = {{a0.x, a0.y}, {a1.x, a1.y}};
                unsigned long long wv[8] = {wA.x, wA.y, wB.x, wB.y,
                                            wC.x, wC.y, wD.x, wD.y};
                #pragma unroll
                for (int q = 0; q < 2; ++q)
                    #pragma unroll
                    for (int e = 0; e < 2; ++e)
                        #pragma unroll
                        for (int j = 0; j < 8; ++j)
                            asm("fma.rn.f32x2 %0, %1, %2, %0;"
                                : "+l"(acc[q][e][j])
                                : "l"(av[q][e]), "l"(wv[j]));
            }
            __syncthreads();
        }

        if (dec) {  // finalize fc: prediction + next-step input
            float ox = oax + bfc, oy = oay + bfc;
            int b2 = tid * 2;
            xsm[b2] = ox; xsm[b2 + 1] = oy;
            int p = t - Tt;
            dout[(b0 + b2) * Pp + p]     = ox;
            dout[(b0 + b2 + 1) * Pp + p] = oy;
            __syncthreads();
        }

        // ---- epilogue: gates, c/h update, store h ----
        #pragma unroll
        for (int q = 0; q < 2; ++q) {
            #pragma unroll
            for (int e = 0; e < 2; ++e) {
                int bb = q * 256 + bg * 4 + e * 2;
                float xt0 = xsm[bb], xt1 = xsm[bb + 1];
                #pragma unroll
                for (int ul = 0; ul < 2; ++ul) {
                    float2 gi = upk(acc[q][e][ul * 4 + 0]);
                    float2 gf = upk(acc[q][e][ul * 4 + 1]);
                    float2 gg = upk(acc[q][e][ul * 4 + 2]);
                    float2 go = upk(acc[q][e][ul * 4 + 3]);
                    int r = rg * 8 + ul * 4;
                    float bi = bsm[r], bf = bsm[r + 1];
                    float bgv = bsm[r + 2], bo = bsm[r + 3];
                    float wi = wis[r], wf = wis[r + 1];
                    float wg = wis[r + 2], wo = wis[r + 3];
                    gi.x += bi + xt0 * wi;   gi.y += bi + xt1 * wi;
                    gf.x += bf + xt0 * wf;   gf.y += bf + xt1 * wf;
                    gg.x += bgv + xt0 * wg;  gg.y += bgv + xt1 * wg;
                    go.x += bo + xt0 * wo;   go.y += bo + xt1 * wo;

                    float c0 = creg[q][e][ul][0];
                    float c1 = creg[q][e][ul][1];
                    c0 = sigm(gf.x) * c0 + sigm(gi.x) * tanhx(gg.x);
                    c1 = sigm(gf.y) * c1 + sigm(gi.y) * tanhx(gg.y);
                    creg[q][e][ul][0] = c0;
                    creg[q][e][ul][1] = c1;
                    float h0 = sigm(go.x) * tanhx(c0);
                    float h1 = sigm(go.y) * tanhx(c1);

                    int gu = u0 + rg * 2 + ul;
                    __stcg((float2*)&hdst[gu * Bb + b0 + bb],
                           make_float2(h0, h1));
                }
            }
        }

        grid_bar();
    }
}

extern "C" void kernel_launch(void* const* d_in, const int* in_sizes, int n_in,
                              void* d_out, int out_size) {
    (void)in_sizes; (void)n_in; (void)out_size;
    cudaFuncSetAttribute(lstm_pers,
                         cudaFuncAttributeMaxDynamicSharedMemorySize,
                         SMEM_BYTES);
    lstm_pers<<<NCTA, NTHR, SMEM_BYTES>>>(
        (const float*)d_in[0],   // x
        (const float*)d_in[1],   // w_ih
        (const float*)d_in[2],   // w_hh
        (const float*)d_in[3],   // b_ih
        (const float*)d_in[4],   // b_hh
        (const float*)d_in[5],   // w_fc
        (const float*)d_in[6],   // b_fc
        (float*)d_out);
}

// round 4
// speedup vs baseline: 1.0004x; 1.0000x over previous
#include <cuda_runtime.h>
#include <cstdint>

#define NCTA 128
#define NTHR 256
#define Bb   1024
#define Tt   512
#define Hh   512
#define Pp   48
#define STEPS (Tt + Pp)
#define BC   512          // batches per CTA
#define RC   32           // gate rows per CTA (8 units x 4 gates)
#define KC   16           // k rows per staged chunk
#define NCHUNK (Hh / KC)  // 32

// ---------------- device scratch (no runtime allocation allowed) ----------
__device__ float             g_h[2][Hh * Bb];  // ping-pong h, [unit][batch]
__device__ float             g_xT[Tt * Bb];    // transposed input x: [t][b]
__device__ unsigned          g_cnt;
__device__ volatile unsigned g_gen;

__device__ __forceinline__ void grid_bar() {
    __syncthreads();
    if (threadIdx.x == 0) {
        __threadfence();
        unsigned gen = g_gen;
        unsigned t = atomicAdd(&g_cnt, 1u);
        if (t == NCTA - 1) {
            g_cnt = 0;
            __threadfence();
            g_gen = gen + 1;
        } else {
            while (g_gen == gen) { __nanosleep(64); }
        }
        __threadfence();
    }
    __syncthreads();
}

__device__ __forceinline__ float sigm(float x) {
    return __fdividef(1.f, 1.f + __expf(-x));
}
__device__ __forceinline__ float tanhx(float x) {
    float e = __expf(-2.f * fabsf(x));
    float t = __fdividef(1.f - e, 1.f + e);
    return copysignf(t, x);
}
__device__ __forceinline__ float2 upk(unsigned long long v) {
    float2 r;
    asm("mov.b64 {%0,%1}, %2;" : "=f"(r.x), "=f"(r.y) : "l"(v));
    return r;
}
__device__ __forceinline__ void cpa16(unsigned dst, const float* src) {
    asm volatile("cp.async.cg.shared.global [%0], [%1], 16;" :: "r"(dst), "l"(src));
}

// SMEM layout (bytes):
//   w2  : [Hh][RC] float2 dup pairs   131072
//   hsm : 2 x [KC][BC] float           65536
//   xsm : [BC] float                    2048
//   wfc : [Hh] float                    2048
//   bsm : [RC] float                     128
//   wis : [RC] float                     128
#define SMEM_BYTES (131072 + 65536 + 2048 + 2048 + 128 + 128)

extern "C" __global__ void __launch_bounds__(NTHR, 1)
lstm_pers(const float* __restrict__ x,
          const float* __restrict__ w_ih,
          const float* __restrict__ w_hh,
          const float* __restrict__ b_ih,
          const float* __restrict__ b_hh,
          const float* __restrict__ w_fc,
          const float* __restrict__ b_fc,
          float* __restrict__ dout)
{
    extern __shared__ __align__(16) char smem_raw[];
    float2* w2  = reinterpret_cast<float2*>(smem_raw);
    float*  hsm = reinterpret_cast<float*>(smem_raw + 131072);
    float*  xsm = hsm + 2 * KC * BC;
    float*  wfc = xsm + BC;
    float*  bsm = wfc + Hh;
    float*  wis = bsm + RC;

    const int tid = threadIdx.x;
    const int ci  = blockIdx.x;
    const int u0  = (ci >> 1) * 8;     // first owned h-unit
    const int b0  = (ci & 1) * BC;     // first owned batch
    const int bg  = tid & 63;          // batch group
    const int rg  = tid >> 6;          // row group (8 rows = 2 units x 4 gates)

    // ---------------- prologue ----------------
    {   // zero h ping buffer 0
        const int per = (Hh * Bb) / NCTA;  // 4096
        float* p = &g_h[0][ci * per];
        for (int i = tid; i < per; i += NTHR) p[i] = 0.f;
    }
    {   // transpose x[b][t] -> g_xT[t][b]
        const int per  = (Bb * Tt) / NCTA; // 4096
        const int base = ci * per;
        for (int i = tid; i < per; i += NTHR) {
            int idx = base + i;
            g_xT[(idx & (Tt - 1)) * Bb + (idx >> 9)] = x[idx];
        }
    }
    {   // owned weight rows -> SMEM, duplicated (w,w)
        int r    = tid >> 3;           // local row 0..31
        int l8   = tid & 7;
        int gate = r & 3, uu = r >> 2;
        int row  = gate * Hh + u0 + uu;
        for (int k = l8; k < Hh; k += 8) {
            float v = w_hh[row * Hh + k];
            w2[k * RC + r] = make_float2(v, v);
        }
        if (l8 == 0) {
            bsm[r] = b_ih[row] + b_hh[row];
            wis[r] = w_ih[row];        // IN == 1
        }
    }
    for (int k = tid; k < Hh; k += NTHR) wfc[k] = w_fc[k];
    const float bfc = b_fc[0];

    float creg[2][2][2][2];            // [quad][pair][unit][lane]
    #pragma unroll
    for (int q = 0; q < 2; q++)
        #pragma unroll
        for (int e = 0; e < 2; e++)
            #pragma unroll
            for (int ul = 0; ul < 2; ul++) {
                creg[q][e][ul][0] = 0.f; creg[q][e][ul][1] = 0.f;
            }

    const unsigned hsm_sa = (unsigned)__cvta_generic_to_shared(hsm);
    const int srow = tid >> 7;         // staging row parity
    const int scol = (tid & 127) * 4;  // staging column (floats)

    grid_bar();

    // ---------------- 560 sequential cell steps ----------------
    for (int t = 0; t < STEPS; ++t) {
        const float* __restrict__ hsrc = g_h[t & 1];
        float* __restrict__       hdst = g_h[(t + 1) & 1];
        const bool dec = (t >= Tt);

        if (!dec)   // encoder input: scalar x per batch
            *(float2*)&xsm[tid * 2] =
                *(const float2*)&g_xT[t * Bb + b0 + tid * 2];

        unsigned long long acc[2][2][8];
        #pragma unroll
        for (int q = 0; q < 2; q++)
            #pragma unroll
            for (int e = 0; e < 2; e++)
                #pragma unroll
                for (int j = 0; j < 8; j++) acc[q][e][j] = 0ull;

        float oax = 0.f, oay = 0.f;    // decoder fc-dot partials

        // stage chunk 0
        {
            const float* src = hsrc + srow * Bb + b0 + scol;
            unsigned dst = hsm_sa + (unsigned)((srow * BC + scol) * 4);
            #pragma unroll
            for (int j = 0; j < 8; ++j)
                cpa16(dst + (unsigned)(j * 2 * BC * 4), src + j * 2 * Bb);
            asm volatile("cp.async.commit_group;");
        }

        for (int c = 0; c < NCHUNK; ++c) {
            if (c + 1 < NCHUNK) {
                const float* src = hsrc + ((c + 1) * KC + srow) * Bb + b0 + scol;
                unsigned dst = hsm_sa +
                    (unsigned)(((((c + 1) & 1) * KC + srow) * BC + scol) * 4);
                #pragma unroll
                for (int j = 0; j < 8; ++j)
                    cpa16(dst + (unsigned)(j * 2 * BC * 4), src + j * 2 * Bb);
                asm volatile("cp.async.commit_group;");
                asm volatile("cp.async.wait_group 1;");
            } else {
                asm volatile("cp.async.wait_group 0;");
            }
            __syncthreads();

            const float* hb = hsm + (c & 1) * KC * BC;

            if (dec) {  // fc(h) dot while the chunk is resident
                #pragma unroll
                for (int kk = 0; kk < KC; ++kk) {
                    float2 hv = *(const float2*)&hb[kk * BC + tid * 2];
                    float  wv = wfc[c * KC + kk];
                    oax = fmaf(hv.x, wv, oax);
                    oay = fmaf(hv.y, wv, oay);
                }
            }

            // GEMM core: packed fp32x2 FMA, batch-paired accumulators
            #pragma unroll
            for (int kk = 0; kk < KC; ++kk) {
                const ulonglong2* wp =
                    (const ulonglong2*)&w2[(c * KC + kk) * RC + rg * 8];
                ulonglong2 wA = wp[0], wB = wp[1], wC = wp[2], wD = wp[3];
                ulonglong2 a0 = *(const ulonglong2*)&hb[kk * BC + bg * 4];
                ulonglong2 a1 = *(const ulonglong2*)&hb[kk * BC + 256 + bg * 4];
                unsigned long long av[2][2] = {{a0.x, a0.y}, {a1.x, a1.y}};
                unsigned long long wv[8] = {wA.x, wA.y, wB.x, wB.y,
                                            wC.x, wC.y, wD.x, wD.y};
                #pragma unroll
                for (int q = 0; q < 2; ++q)
                    #pragma unroll
                    for (int e = 0; e < 2; ++e)
                        #pragma unroll
                        for (int j = 0; j < 8; ++j)
                            asm("fma.rn.f32x2 %0, %1, %2, %0;"
                                : "+l"(acc[q][e][j])
                                : "l"(av[q][e]), "l"(wv[j]));
            }
            __syncthreads();
        }

        if (dec) {  // finalize fc: prediction + next-step input
            float ox = oax + bfc, oy = oay + bfc;
            int b2 = tid * 2;
            xsm[b2] = ox; xsm[b2 + 1] = oy;
            int p = t - Tt;
            dout[(b0 + b2) * Pp + p]     = ox;
            dout[(b0 + b2 + 1) * Pp + p] = oy;
            __syncthreads();
        }

        // ---- epilogue: gates, c/h update, store h ----
        #pragma unroll
        for (int q = 0; q < 2; ++q) {
            #pragma unroll
            for (int e = 0; e < 2; ++e) {
                int bb = q * 256 + bg * 4 + e * 2;
                float xt0 = xsm[bb], xt1 = xsm[bb + 1];
                #pragma unroll
                for (int ul = 0; ul < 2; ++ul) {
                    float2 gi = upk(acc[q][e][ul * 4 + 0]);
                    float2 gf = upk(acc[q][e][ul * 4 + 1]);
                    float2 gg = upk(acc[q][e][ul * 4 + 2]);
                    float2 go = upk(acc[q][e][ul * 4 + 3]);
                    int r = rg * 8 + ul * 4;
                    float bi = bsm[r], bf = bsm[r + 1];
                    float bgv = bsm[r + 2], bo = bsm[r + 3];
                    float wi = wis[r], wf = wis[r + 1];
                    float wg = wis[r + 2], wo = wis[r + 3];
                    gi.x += bi + xt0 * wi;   gi.y += bi + xt1 * wi;
                    gf.x += bf + xt0 * wf;   gf.y += bf + xt1 * wf;
                    gg.x += bgv + xt0 * wg;  gg.y += bgv + xt1 * wg;
                    go.x += bo + xt0 * wo;   go.y += bo + xt1 * wo;

                    float c0 = creg[q][e][ul][0];
                    float c1 = creg[q][e][ul][1];
                    c0 = sigm(gf.x) * c0 + sigm(gi.x) * tanhx(gg.x);
                    c1 = sigm(gf.y) * c1 + sigm(gi.y) * tanhx(gg.y);
                    creg[q][e][ul][0] = c0;
                    creg[q][e][ul][1] = c1;
                    float h0 = sigm(go.x) * tanhx(c0);
                    float h1 = sigm(go.y) * tanhx(c1);

                    int gu = u0 + rg * 2 + ul;
                    __stcg((float2*)&hdst[gu * Bb + b0 + bb],
                           make_float2(h0, h1));
                }
            }
        }

        grid_bar();
    }
}

extern "C" void kernel_launch(void* const* d_in, const int* in_sizes, int n_in,
                              void* d_out, int out_size) {
    (void)in_sizes; (void)n_in; (void)out_size;
    cudaFuncSetAttribute(lstm_pers,
                         cudaFuncAttributeMaxDynamicSharedMemorySize,
                         SMEM_BYTES);
    lstm_pers<<<NCTA, NTHR, SMEM_BYTES>>>(
        (const float*)d_in[0],   // x
        (const float*)d_in[1],   // w_ih
        (const float*)d_in[2],   // w_hh
        (const float*)d_in[3],   // b_ih
        (const float*)d_in[4],   // b_hh
        (const float*)d_in[5],   // w_fc
        (const float*)d_in[6],   // b_fc
        (float*)d_out);
}

// round 6
// speedup vs baseline: 1.7752x; 1.7745x over previous
#include <cuda_runtime.h>
#include <cuda_fp16.h>
#include <cstdint>

#define NCTA 128
#define NTHR 256

// ---------------- device scratch ----------------
__device__ __align__(128) unsigned char g_hpack[2097152]; // [b1024][k512] fp16: hi @0, lo @1MB
__device__ __align__(128) unsigned char g_wpack[4194304]; // [n2048][k512] fp16: hi @0, lo @2MB
__device__ float g_xT[512 * 1024];
__device__ float g_xdec[48 * 1024];
__device__ unsigned g_cnt;
__device__ volatile unsigned g_gen;

__device__ __forceinline__ void grid_bar() {
    __syncthreads();
    if (threadIdx.x == 0) {
        __threadfence();
        unsigned gen = g_gen;
        unsigned t = atomicAdd(&g_cnt, 1u);
        if (t == NCTA - 1) { g_cnt = 0; __threadfence(); g_gen = gen + 1; }
        else { while (g_gen == gen) { __nanosleep(64); } }
        __threadfence();
    }
    __syncthreads();
}

__device__ __forceinline__ float sigm(float x) {
    return __fdividef(1.f, 1.f + __expf(-x));
}
__device__ __forceinline__ float tanhx(float x) {
    float e = __expf(-2.f * fabsf(x));
    return copysignf(__fdividef(1.f - e, 1.f + e), x);
}
__device__ __forceinline__ void cpa16(unsigned dst, const void* src) {
    asm volatile("cp.async.cg.shared.global [%0], [%1], 16;" :: "r"(dst), "l"(src));
}
__device__ __forceinline__ void ldmx4(uint32_t& r0, uint32_t& r1, uint32_t& r2,
                                      uint32_t& r3, unsigned a) {
    asm volatile("ldmatrix.sync.aligned.m8n8.x4.shared.b16 {%0,%1,%2,%3}, [%4];"
        : "=r"(r0), "=r"(r1), "=r"(r2), "=r"(r3) : "r"(a));
}
__device__ __forceinline__ void mma16816(float* d, const uint32_t* a,
                                         uint32_t b0, uint32_t b1) {
    asm volatile("mma.sync.aligned.m16n8k16.row.col.f32.f16.f16.f32 "
        "{%0,%1,%2,%3}, {%4,%5,%6,%7}, {%8,%9}, {%0,%1,%2,%3};"
        : "+f"(d[0]), "+f"(d[1]), "+f"(d[2]), "+f"(d[3])
        : "r"(a[0]), "r"(a[1]), "r"(a[2]), "r"(a[3]), "r"(b0), "r"(b1));
}

// ---------------- prologue kernels ----------------
extern "C" __global__ void prep_k(const float* __restrict__ x) {
    int n = blockIdx.x * 256 + threadIdx.x;          // 0..524287
    int b = n >> 9, t = n & 511;
    g_xT[t * 1024 + b] = x[n];                       // x[b][t][0]
    ((uint32_t*)g_hpack)[n] = 0u;                    // zero both h planes (2MB)
    if (n < 48 * 1024) g_xdec[n] = 0.f;
}

extern "C" __global__ void pack_w(const float* __restrict__ w_hh) {
    int n = blockIdx.x * 256 + threadIdx.x;          // 0..1048575
    int k = n & 511, ng = n >> 9;
    int j = ng >> 7, nl = ng & 127;
    int wn = nl >> 5, gate = (nl >> 3) & 3, ul = nl & 7;
    int row = gate * 512 + j * 32 + wn * 8 + ul;
    float w = w_hh[row * 512 + k];
    __half hi = __float2half_rn(w);
    __half lo = __float2half_rn(w - __half2float(hi));
    __half* wp = (__half*)g_wpack;
    wp[ng * 512 + k] = hi;
    wp[1048576 + ng * 512 + k] = lo;
}

// ---------------- GEMM pass: one (A,B) panel pair, k=64 ----------------
__device__ __forceinline__ void gemm_pass(unsigned Ap, unsigned Bp,
    float (&D)[4][4][4], unsigned thA, unsigned thB, int qsel, int sw7)
{
    #pragma unroll
    for (int k16 = 0; k16 < 4; ++k16) {
        unsigned swz = (unsigned)((((k16 * 2 + qsel) ^ sw7)) << 4);
        uint32_t Bf[4][2];
        #pragma unroll
        for (int nb = 0; nb < 2; ++nb) {
            uint32_t r0, r1, r2, r3;
            ldmx4(r0, r1, r2, r3, Bp + thB + nb * 2048 + swz);
            Bf[2 * nb][0] = r0; Bf[2 * nb][1] = r2;
            Bf[2 * nb + 1][0] = r1; Bf[2 * nb + 1][1] = r3;
        }
        #pragma unroll
        for (int mt = 0; mt < 4; ++mt) {
            uint32_t a[4];
            ldmx4(a[0], a[1], a[2], a[3], Ap + thA + mt * 2048 + swz);
            #pragma unroll
            for (int nt = 0; nt < 4; ++nt)
                mma16816(D[mt][nt], a, Bf[nt][0], Bf[nt][1]);
        }
    }
}

// ---------------- main persistent kernel ----------------
#define SMEM_MAIN 131072

extern "C" __global__ void __launch_bounds__(256, 1)
lstm_mma(const float* __restrict__ w_ih, const float* __restrict__ b_ih,
         const float* __restrict__ b_hh, const float* __restrict__ w_fc,
         const float* __restrict__ b_fc, float* __restrict__ dout)
{
    extern __shared__ __align__(1024) char smem[];
    const unsigned sa = (unsigned)__cvta_generic_to_shared(smem);

    const int tid = threadIdx.x;
    const int lane = tid & 31, w = tid >> 5;
    const int wm = w >> 2, wn = w & 3;
    const int ql = lane & 3, qr = lane >> 2;
    const int i = blockIdx.x & 7, j = blockIdx.x >> 3;

    // per-thread constants: bias, w_ih, w_fc for its 2 units x 4 gates
    float bs[4][2], ws[4][2], wfc_r[2];
    #pragma unroll
    for (int d = 0; d < 2; ++d) {
        int u = j * 32 + wn * 8 + 2 * ql + d;
        wfc_r[d] = w_fc[u];
        #pragma unroll
        for (int g = 0; g < 4; ++g) {
            int row = g * 512 + u;
            bs[g][d] = b_ih[row] + b_hh[row];
            ws[g][d] = w_ih[row];
        }
    }
    const float bfc = b_fc[0];
    int bth[4][2];
    #pragma unroll
    for (int mt = 0; mt < 4; ++mt)
        #pragma unroll
        for (int hh = 0; hh < 2; ++hh)
            bth[mt][hh] = i * 128 + wm * 64 + mt * 16 + qr + 8 * hh;
    const int kpos = j * 32 + wn * 8 + 2 * ql;   // this thread's k-slot in h_pack

    // staging (cp.async) parameters
    const int sr = tid >> 1, sq = tid & 1;
    const char* pA0 = (const char*)g_hpack + (size_t)(i * 128 + sr) * 1024 + sq * 64;
    const char* pA1 = pA0 + 1048576;
    const char* pB0 = (const char*)g_wpack + (size_t)(j * 128 + sr) * 1024 + sq * 64;
    const char* pB1 = pB0 + 2097152;
    const unsigned sdst = sa + sr * 128;
    unsigned swo[4];
    #pragma unroll
    for (int qq = 0; qq < 4; ++qq)
        swo[qq] = (unsigned)((((sq * 4 + qq) ^ (sr & 7))) << 4);

    // ldmatrix thread bases
    const int rl = lane & 15, qsel = lane >> 4, sw7 = rl & 7;
    const unsigned thA = (unsigned)((wm * 64 + rl) * 128);
    const unsigned thB = (unsigned)((wn * 32 + rl) * 128);

    float cst[4][4];
    #pragma unroll
    for (int mt = 0; mt < 4; ++mt)
        #pragma unroll
        for (int e = 0; e < 4; ++e) cst[mt][e] = 0.f;

    #define LOADCHUNK(c, s) do {                                              \
        unsigned _db = sdst + (unsigned)((s) * 65536);                         \
        const char* _a0 = pA0 + (c) * 128;                                     \
        const char* _a1 = pA1 + (c) * 128;                                     \
        const char* _b0 = pB0 + (c) * 128;                                     \
        const char* _b1 = pB1 + (c) * 128;                                     \
        _Pragma("unroll")                                                      \
        for (int qq = 0; qq < 4; ++qq) {                                       \
            cpa16(_db +         swo[qq], _a0 + qq * 16);                       \
            cpa16(_db + 16384 + swo[qq], _a1 + qq * 16);                       \
            cpa16(_db + 32768 + swo[qq], _b0 + qq * 16);                       \
            cpa16(_db + 49152 + swo[qq], _b1 + qq * 16);                       \
        }                                                                      \
        asm volatile("cp.async.commit_group;" ::: "memory");                   \
    } while (0)

    for (int t = 0; t < 560; ++t) {
        // ---- step input ----
        float xtv[4][2];
        if (t < 512) {
            #pragma unroll
            for (int mt = 0; mt < 4; ++mt)
                #pragma unroll
                for (int hh = 0; hh < 2; ++hh)
                    xtv[mt][hh] = g_xT[t * 1024 + bth[mt][hh]];
        } else {
            int p = t - 512;
            #pragma unroll
            for (int mt = 0; mt < 4; ++mt)
                #pragma unroll
                for (int hh = 0; hh < 2; ++hh) {
                    xtv[mt][hh] = g_xdec[p * 1024 + bth[mt][hh]] + bfc;
                    if (j == 0 && wn == 0 && ql == 0)
                        dout[bth[mt][hh] * 48 + p] = xtv[mt][hh];
                }
            if (t == 559) break;
        }

        float D[4][4][4];
        #pragma unroll
        for (int mt = 0; mt < 4; ++mt)
            #pragma unroll
            for (int nt = 0; nt < 4; ++nt)
                #pragma unroll
                for (int e = 0; e < 4; ++e) D[mt][nt][e] = 0.f;

        // ---- GEMM: 8 double-buffered k64 chunks, 3 hi/lo passes each ----
        LOADCHUNK(0, 0);
        for (int c = 0; c < 8; ++c) {
            if (c < 7) {
                LOADCHUNK(c + 1, (c + 1) & 1);
                asm volatile("cp.async.wait_group 1;" ::: "memory");
            } else {
                asm volatile("cp.async.wait_group 0;" ::: "memory");
            }
            __syncthreads();
            unsigned st = sa + (unsigned)((c & 1) * 65536);
            gemm_pass(st,         st + 32768, D, thA, thB, qsel, sw7); // h_hi * w_hi
            gemm_pass(st + 16384, st + 32768, D, thA, thB, qsel, sw7); // h_lo * w_hi
            gemm_pass(st,         st + 49152, D, thA, thB, qsel, sw7); // h_hi * w_lo
            __syncthreads();
        }

        // ---- epilogue: gates, c/h update, h hi/lo store, fc ----
        #pragma unroll
        for (int mt = 0; mt < 4; ++mt) {
            #pragma unroll
            for (int hh = 0; hh < 2; ++hh) {
                float xt = xtv[mt][hh];
                float hv2[2];
                #pragma unroll
                for (int d = 0; d < 2; ++d) {
                    int e = hh * 2 + d;
                    float gi = D[mt][0][e] + bs[0][d] + xt * ws[0][d];
                    float gf = D[mt][1][e] + bs[1][d] + xt * ws[1][d];
                    float gg = D[mt][2][e] + bs[2][d] + xt * ws[2][d];
                    float go = D[mt][3][e] + bs[3][d] + xt * ws[3][d];
                    float c2 = sigm(gf) * cst[mt][e] + sigm(gi) * tanhx(gg);
                    cst[mt][e] = c2;
                    hv2[d] = sigm(go) * tanhx(c2);
                }
                __half h0 = __float2half_rn(hv2[0]);
                __half h1 = __float2half_rn(hv2[1]);
                uint32_t hiu = (uint32_t)__half_as_ushort(h0) |
                               ((uint32_t)__half_as_ushort(h1) << 16);
                __half l0 = __float2half_rn(hv2[0] - __half2float(h0));
                __half l1 = __float2half_rn(hv2[1] - __half2float(h1));
                uint32_t lou = (uint32_t)__half_as_ushort(l0) |
                               ((uint32_t)__half_as_ushort(l1) << 16);
                size_t off = (size_t)bth[mt][hh] * 1024 + (size_t)kpos * 2;
                *(uint32_t*)((char*)g_hpack + off)           = hiu;
                *(uint32_t*)((char*)g_hpack + 1048576 + off) = lou;

                if (t >= 511 && t < 559) {
                    float pa = hv2[0] * wfc_r[0] + hv2[1] * wfc_r[1];
                    pa += __shfl_xor_sync(0xFFFFFFFFu, pa, 1);
                    pa += __shfl_xor_sync(0xFFFFFFFFu, pa, 2);
                    if (ql == 0)
                        atomicAdd(&g_xdec[(t - 511) * 1024 + bth[mt][hh]], pa);
                }
            }
        }

        grid_bar();
    }
    #undef LOADCHUNK
}

extern "C" void kernel_launch(void* const* d_in, const int* in_sizes, int n_in,
                              void* d_out, int out_size) {
    (void)in_sizes; (void)n_in; (void)out_size;
    cudaFuncSetAttribute(lstm_mma, cudaFuncAttributeMaxDynamicSharedMemorySize,
                         SMEM_MAIN);
    prep_k<<<2048, 256>>>((const float*)d_in[0]);
    pack_w<<<4096, 256>>>((const float*)d_in[2]);
    lstm_mma<<<NCTA, 256, SMEM_MAIN>>>(
        (const float*)d_in[1],   // w_ih
        (const float*)d_in[3],   // b_ih
        (const float*)d_in[4],   // b_hh
        (const float*)d_in[5],   // w_fc
        (const float*)d_in[6],   // b_fc
        (float*)d_out);
}

// round 7
// speedup vs baseline: 2.6724x; 1.5054x over previous
#include <cuda_runtime.h>
#include <cuda_fp16.h>
#include <cstdint>

#define NCTA 128
#define OFF_STA 131072                 // after 128KB resident w_hi
#define SMEM_MAIN (131072 + 2 * 32768) // 196608

// ---------------- device scratch ----------------
__device__ __align__(128) unsigned char g_hpack[2097152]; // [b1024][k512] fp16: hi @0, lo @1MB
__device__ __align__(128) unsigned char g_wpack[2097152]; // [n2048 perm][k512] fp16 hi
__device__ float g_xT[512 * 1024];
__device__ float g_xdec[48 * 1024];
__device__ unsigned g_cnt;
__device__ volatile unsigned g_gen;

__device__ __forceinline__ void grid_bar() {
    __syncthreads();
    if (threadIdx.x == 0) {
        __threadfence();
        unsigned gen = g_gen;
        unsigned t = atomicAdd(&g_cnt, 1u);
        if (t == NCTA - 1) { g_cnt = 0; __threadfence(); g_gen = gen + 1; }
        else { while (g_gen == gen) { __nanosleep(64); } }
        __threadfence();
    }
    __syncthreads();
}

__device__ __forceinline__ float sigm(float x) {
    return __fdividef(1.f, 1.f + __expf(-x));
}
__device__ __forceinline__ float tanhx(float x) {
    float e = __expf(-2.f * fabsf(x));
    return copysignf(__fdividef(1.f - e, 1.f + e), x);
}
__device__ __forceinline__ void cpa16(unsigned dst, const void* src) {
    asm volatile("cp.async.cg.shared.global [%0], [%1], 16;" :: "r"(dst), "l"(src));
}
__device__ __forceinline__ void ldmx4(uint32_t& r0, uint32_t& r1, uint32_t& r2,
                                      uint32_t& r3, unsigned a) {
    asm volatile("ldmatrix.sync.aligned.m8n8.x4.shared.b16 {%0,%1,%2,%3}, [%4];"
        : "=r"(r0), "=r"(r1), "=r"(r2), "=r"(r3) : "r"(a));
}
__device__ __forceinline__ void mma16816(float* d, const uint32_t* a,
                                         uint32_t b0, uint32_t b1) {
    asm volatile("mma.sync.aligned.m16n8k16.row.col.f32.f16.f16.f32 "
        "{%0,%1,%2,%3}, {%4,%5,%6,%7}, {%8,%9}, {%0,%1,%2,%3};"
        : "+f"(d[0]), "+f"(d[1]), "+f"(d[2]), "+f"(d[3])
        : "r"(a[0]), "r"(a[1]), "r"(a[2]), "r"(a[3]), "r"(b0), "r"(b1));
}

// ---------------- prologue kernels ----------------
extern "C" __global__ void prep_k(const float* __restrict__ x) {
    int n = blockIdx.x * 256 + threadIdx.x;          // 0..524287
    int b = n >> 9, t = n & 511;
    g_xT[t * 1024 + b] = x[n];                       // x[b][t][0]
    ((uint32_t*)g_hpack)[n] = 0u;                    // zero both h planes (2MB)
    if (n < 48 * 1024) g_xdec[n] = 0.f;
}

extern "C" __global__ void pack_w(const float* __restrict__ w_hh) {
    int n = blockIdx.x * 256 + threadIdx.x;          // 0..1048575
    int k = n & 511, ng = n >> 9;
    int j = ng >> 7, nl = ng & 127;
    int wn = nl >> 5, gate = (nl >> 3) & 3, ul = nl & 7;
    int row = gate * 512 + j * 32 + wn * 8 + ul;
    ((__half*)g_wpack)[ng * 512 + k] = __float2half_rn(w_hh[row * 512 + k]);
}

// ---------------- main persistent kernel ----------------
extern "C" __global__ void __launch_bounds__(256, 1)
lstm_mma(const float* __restrict__ w_ih, const float* __restrict__ b_ih,
         const float* __restrict__ b_hh, const float* __restrict__ w_fc,
         const float* __restrict__ b_fc, float* __restrict__ dout)
{
    extern __shared__ __align__(1024) char smem[];
    const unsigned sa = (unsigned)__cvta_generic_to_shared(smem);

    const int tid = threadIdx.x;
    const int lane = tid & 31, w = tid >> 5;
    const int wm = w >> 2, wn = w & 3;
    const int ql = lane & 3, qr = lane >> 2;
    const int i = blockIdx.x & 7, j = blockIdx.x >> 3;

    // per-thread constants: bias, w_ih, w_fc for its 2 units x 4 gates
    float bs[4][2], ws[4][2], wfc_r[2];
    #pragma unroll
    for (int d = 0; d < 2; ++d) {
        int u = j * 32 + wn * 8 + 2 * ql + d;
        wfc_r[d] = w_fc[u];
        #pragma unroll
        for (int g = 0; g < 4; ++g) {
            int row = g * 512 + u;
            bs[g][d] = b_ih[row] + b_hh[row];
            ws[g][d] = w_ih[row];
        }
    }
    const float bfc = b_fc[0];
    int bth[4][2];
    #pragma unroll
    for (int mt = 0; mt < 4; ++mt)
        #pragma unroll
        for (int hh = 0; hh < 2; ++hh)
            bth[mt][hh] = i * 128 + wm * 64 + mt * 16 + qr + 8 * hh;
    const int kpos = j * 32 + wn * 8 + 2 * ql;   // this thread's k-slot in h_pack

    // ---- resident w_hi: 8 panels of [128 rows][64 k] fp16, SW128 swizzled ----
    for (int idx = tid; idx < 8192; idx += 256) {
        int c = idx >> 10, r = (idx >> 3) & 127, q = idx & 7;
        unsigned dst = sa + (unsigned)(c * 16384 + r * 128 + ((q ^ (r & 7)) * 16));
        const char* src = (const char*)g_wpack +
            ((size_t)(j * 128 + r)) * 1024 + c * 128 + q * 16;
        cpa16(dst, src);
    }
    asm volatile("cp.async.commit_group;\n\tcp.async.wait_group 0;" ::: "memory");
    __syncthreads();

    // staging (cp.async) parameters for A (h hi/lo)
    const int sr = tid >> 1, sq = tid & 1;
    const char* pA0 = (const char*)g_hpack + (size_t)(i * 128 + sr) * 1024 + sq * 64;
    const char* pA1 = pA0 + 1048576;
    const unsigned sdst = sa + OFF_STA + (unsigned)(sr * 128);
    unsigned swo[4];
    #pragma unroll
    for (int qq = 0; qq < 4; ++qq)
        swo[qq] = (unsigned)((((sq * 4 + qq) ^ (sr & 7))) << 4);

    // ldmatrix thread bases
    const int rl = lane & 15, qsel = lane >> 4, sw7 = rl & 7;
    const unsigned thA = (unsigned)((wm * 64 + rl) * 128);
    const unsigned thB = (unsigned)((wn * 32 + rl) * 128);

    float cst[4][4];
    #pragma unroll
    for (int mt = 0; mt < 4; ++mt)
        #pragma unroll
        for (int e = 0; e < 4; ++e) cst[mt][e] = 0.f;

    #define LOADCHUNK(c, s) do {                                              \
        unsigned _db = sdst + (unsigned)((s) * 32768);                         \
        const char* _a0 = pA0 + (c) * 128;                                     \
        const char* _a1 = pA1 + (c) * 128;                                     \
        _Pragma("unroll")                                                      \
        for (int qq = 0; qq < 4; ++qq) {                                       \
            cpa16(_db +         swo[qq], _a0 + qq * 16);                       \
            cpa16(_db + 16384 + swo[qq], _a1 + qq * 16);                       \
        }                                                                      \
        asm volatile("cp.async.commit_group;" ::: "memory");                   \
    } while (0)

    for (int t = 0; t < 560; ++t) {
        // ---- step input ----
        float xtv[4][2];
        if (t < 512) {
            #pragma unroll
            for (int mt = 0; mt < 4; ++mt)
                #pragma unroll
                for (int hh = 0; hh < 2; ++hh)
                    xtv[mt][hh] = g_xT[t * 1024 + bth[mt][hh]];
        } else {
            int p = t - 512;
            #pragma unroll
            for (int mt = 0; mt < 4; ++mt)
                #pragma unroll
                for (int hh = 0; hh < 2; ++hh) {
                    xtv[mt][hh] = g_xdec[p * 1024 + bth[mt][hh]] + bfc;
                    if (j == 0 && wn == 0 && ql == 0)
                        dout[bth[mt][hh] * 48 + p] = xtv[mt][hh];
                }
            if (t == 559) break;
        }

        float D[4][4][4];
        #pragma unroll
        for (int mt = 0; mt < 4; ++mt)
            #pragma unroll
            for (int nt = 0; nt < 4; ++nt)
                #pragma unroll
                for (int e = 0; e < 4; ++e) D[mt][nt][e] = 0.f;

        // ---- GEMM: 8 double-buffered A-k64 chunks, 2 passes (h_hi,h_lo) x resident w_hi
        LOADCHUNK(0, 0);
        for (int c = 0; c < 8; ++c) {
            if (c < 7) {
                LOADCHUNK(c + 1, (c + 1) & 1);
                asm volatile("cp.async.wait_group 1;" ::: "memory");
            } else {
                asm volatile("cp.async.wait_group 0;" ::: "memory");
            }
            __syncthreads();
            const unsigned stA = sa + OFF_STA + (unsigned)((c & 1) * 32768);
            const unsigned stB = sa + (unsigned)(c * 16384);
            #pragma unroll
            for (int k16 = 0; k16 < 4; ++k16) {
                unsigned swz = (unsigned)((((k16 * 2 + qsel) ^ sw7)) << 4);
                uint32_t Bf[4][2];
                #pragma unroll
                for (int nb = 0; nb < 2; ++nb) {
                    uint32_t r0, r1, r2, r3;
                    ldmx4(r0, r1, r2, r3, stB + thB + nb * 2048 + swz);
                    Bf[2 * nb][0] = r0; Bf[2 * nb][1] = r2;
                    Bf[2 * nb + 1][0] = r1; Bf[2 * nb + 1][1] = r3;
                }
                #pragma unroll
                for (int pass = 0; pass < 2; ++pass) {
                    unsigned Ap = stA + (unsigned)(pass * 16384);
                    #pragma unroll
                    for (int mt = 0; mt < 4; ++mt) {
                        uint32_t a[4];
                        ldmx4(a[0], a[1], a[2], a[3], Ap + thA + mt * 2048 + swz);
                        #pragma unroll
                        for (int nt = 0; nt < 4; ++nt)
                            mma16816(D[mt][nt], a, Bf[nt][0], Bf[nt][1]);
                    }
                }
            }
            __syncthreads();
        }

        // ---- epilogue: gates, c/h update, h hi/lo store, fc ----
        #pragma unroll
        for (int mt = 0; mt < 4; ++mt) {
            #pragma unroll
            for (int hh = 0; hh < 2; ++hh) {
                float xt = xtv[mt][hh];
                float hv2[2];
                #pragma unroll
                for (int d = 0; d < 2; ++d) {
                    int e = hh * 2 + d;
                    float gi = D[mt][0][e] + bs[0][d] + xt * ws[0][d];
                    float gf = D[mt][1][e] + bs[1][d] + xt * ws[1][d];
                    float gg = D[mt][2][e] + bs[2][d] + xt * ws[2][d];
                    float go = D[mt][3][e] + bs[3][d] + xt * ws[3][d];
                    float c2 = sigm(gf) * cst[mt][e] + sigm(gi) * tanhx(gg);
                    cst[mt][e] = c2;
                    hv2[d] = sigm(go) * tanhx(c2);
                }
                __half h0 = __float2half_rn(hv2[0]);
                __half h1 = __float2half_rn(hv2[1]);
                uint32_t hiu = (uint32_t)__half_as_ushort(h0) |
                               ((uint32_t)__half_as_ushort(h1) << 16);
                __half l0 = __float2half_rn(hv2[0] - __half2float(h0));
                __half l1 = __float2half_rn(hv2[1] - __half2float(h1));
                uint32_t lou = (uint32_t)__half_as_ushort(l0) |
                               ((uint32_t)__half_as_ushort(l1) << 16);
                size_t off = (size_t)bth[mt][hh] * 1024 + (size_t)kpos * 2;
                *(uint32_t*)((char*)g_hpack + off)           = hiu;
                *(uint32_t*)((char*)g_hpack + 1048576 + off) = lou;

                if (t >= 511 && t < 559) {
                    float pa = hv2[0] * wfc_r[0] + hv2[1] * wfc_r[1];
                    pa += __shfl_xor_sync(0xFFFFFFFFu, pa, 1);
                    pa += __shfl_xor_sync(0xFFFFFFFFu, pa, 2);
                    if (ql == 0)
                        atomicAdd(&g_xdec[(t - 511) * 1024 + bth[mt][hh]], pa);
                }
            }
        }

        grid_bar();
    }
    #undef LOADCHUNK
}

extern "C" void kernel_launch(void* const* d_in, const int* in_sizes, int n_in,
                              void* d_out, int out_size) {
    (void)in_sizes; (void)n_in; (void)out_size;
    cudaFuncSetAttribute(lstm_mma, cudaFuncAttributeMaxDynamicSharedMemorySize,
                         SMEM_MAIN);
    prep_k<<<2048, 256>>>((const float*)d_in[0]);
    pack_w<<<4096, 256>>>((const float*)d_in[2]);
    lstm_mma<<<NCTA, 256, SMEM_MAIN>>>(
        (const float*)d_in[1],   // w_ih
        (const float*)d_in[3],   // b_ih
        (const float*)d_in[4],   // b_hh
        (const float*)d_in[5],   // w_fc
        (const float*)d_in[6],   // b_fc
        (float*)d_out);
}

// round 8
// speedup vs baseline: 4.4509x; 1.6655x over previous
#include <cuda_runtime.h>
#include <cuda_fp16.h>
#include <cstdint>

#define NCTA 128
#define OFF_STA 131072                 // after 128KB resident w_hi
#define SMEM_MAIN (131072 + 2 * 16384) // 163840

// ---------------- device scratch ----------------
__device__ __align__(128) unsigned char g_hpack[1048576]; // [b1024][k512] fp16 h
__device__ __align__(128) unsigned char g_wpack[2097152]; // [n2048 perm][k512] fp16 w
__device__ float g_xT[512 * 1024];
__device__ float g_xdec[48 * 1024];
__device__ unsigned g_cnt;
__device__ volatile unsigned g_gen;

__device__ __forceinline__ void grid_bar() {
    __syncthreads();
    if (threadIdx.x == 0) {
        __threadfence();
        unsigned gen = g_gen;
        unsigned t = atomicAdd(&g_cnt, 1u);
        if (t == NCTA - 1) { g_cnt = 0; __threadfence(); g_gen = gen + 1; }
        else { while (g_gen == gen) { __nanosleep(64); } }
        __threadfence();
    }
    __syncthreads();
}

__device__ __forceinline__ float sigm(float x) {
    return __fdividef(1.f, 1.f + __expf(-x));
}
__device__ __forceinline__ float tanhx(float x) {
    float e = __expf(-2.f * fabsf(x));
    return copysignf(__fdividef(1.f - e, 1.f + e), x);
}
__device__ __forceinline__ void cpa16(unsigned dst, const void* src) {
    asm volatile("cp.async.cg.shared.global [%0], [%1], 16;" :: "r"(dst), "l"(src));
}
__device__ __forceinline__ void ldmx4(uint32_t& r0, uint32_t& r1, uint32_t& r2,
                                      uint32_t& r3, unsigned a) {
    asm volatile("ldmatrix.sync.aligned.m8n8.x4.shared.b16 {%0,%1,%2,%3}, [%4];"
        : "=r"(r0), "=r"(r1), "=r"(r2), "=r"(r3) : "r"(a));
}
__device__ __forceinline__ void mma16816(float* d, const uint32_t* a,
                                         uint32_t b0, uint32_t b1) {
    asm volatile("mma.sync.aligned.m16n8k16.row.col.f32.f16.f16.f32 "
        "{%0,%1,%2,%3}, {%4,%5,%6,%7}, {%8,%9}, {%0,%1,%2,%3};"
        : "+f"(d[0]), "+f"(d[1]), "+f"(d[2]), "+f"(d[3])
        : "r"(a[0]), "r"(a[1]), "r"(a[2]), "r"(a[3]), "r"(b0), "r"(b1));
}

// ---------------- prologue kernels ----------------
extern "C" __global__ void prep_k(const float* __restrict__ x) {
    int n = blockIdx.x * 256 + threadIdx.x;          // 0..524287
    int b = n >> 9, t = n & 511;
    g_xT[t * 1024 + b] = x[n];                       // x[b][t][0]
    if (n < 262144) ((uint32_t*)g_hpack)[n] = 0u;    // zero h plane (1MB)
    if (n < 48 * 1024) g_xdec[n] = 0.f;
}

extern "C" __global__ void pack_w(const float* __restrict__ w_hh) {
    int n = blockIdx.x * 256 + threadIdx.x;          // 0..1048575
    int k = n & 511, ng = n >> 9;
    int j = ng >> 7, nl = ng & 127;
    int wn = nl >> 5, gate = (nl >> 3) & 3, ul = nl & 7;
    int row = gate * 512 + j * 32 + wn * 8 + ul;
    ((__half*)g_wpack)[ng * 512 + k] = __float2half_rn(w_hh[row * 512 + k]);
}

// ---------------- main persistent kernel ----------------
extern "C" __global__ void __launch_bounds__(256, 1)
lstm_mma(const float* __restrict__ w_ih, const float* __restrict__ b_ih,
         const float* __restrict__ b_hh, const float* __restrict__ w_fc,
         const float* __restrict__ b_fc, float* __restrict__ dout)
{
    extern __shared__ __align__(1024) char smem[];
    const unsigned sa = (unsigned)__cvta_generic_to_shared(smem);

    const int tid = threadIdx.x;
    const int lane = tid & 31, w = tid >> 5;
    const int wm = w >> 2, wn = w & 3;
    const int ql = lane & 3, qr = lane >> 2;
    const int i = blockIdx.x & 7, j = blockIdx.x >> 3;

    // per-thread constants: bias, w_ih, w_fc for its 2 units x 4 gates
    float bs[4][2], ws[4][2], wfc_r[2];
    #pragma unroll
    for (int d = 0; d < 2; ++d) {
        int u = j * 32 + wn * 8 + 2 * ql + d;
        wfc_r[d] = w_fc[u];
        #pragma unroll
        for (int g = 0; g < 4; ++g) {
            int row = g * 512 + u;
            bs[g][d] = b_ih[row] + b_hh[row];
            ws[g][d] = w_ih[row];
        }
    }
    const float bfc = b_fc[0];
    int bth[4][2];
    #pragma unroll
    for (int mt = 0; mt < 4; ++mt)
        #pragma unroll
        for (int hh = 0; hh < 2; ++hh)
            bth[mt][hh] = i * 128 + wm * 64 + mt * 16 + qr + 8 * hh;
    const int kpos = j * 32 + wn * 8 + 2 * ql;   // this thread's k-slot in h_pack

    // ---- resident w_hi: 8 panels of [128 rows][64 k] fp16, SW128 swizzled ----
    for (int idx = tid; idx < 8192; idx += 256) {
        int c = idx >> 10, r = (idx >> 3) & 127, q = idx & 7;
        unsigned dst = sa + (unsigned)(c * 16384 + r * 128 + ((q ^ (r & 7)) * 16));
        const char* src = (const char*)g_wpack +
            ((size_t)(j * 128 + r)) * 1024 + c * 128 + q * 16;
        cpa16(dst, src);
    }
    asm volatile("cp.async.commit_group;\n\tcp.async.wait_group 0;" ::: "memory");
    __syncthreads();

    // staging (cp.async) parameters for A (h fp16), 16KB per chunk
    const int sr = tid >> 1, sq = tid & 1;
    const char* pA0 = (const char*)g_hpack + (size_t)(i * 128 + sr) * 1024 + sq * 64;
    const unsigned sdst = sa + OFF_STA + (unsigned)(sr * 128);
    unsigned swo[4];
    #pragma unroll
    for (int qq = 0; qq < 4; ++qq)
        swo[qq] = (unsigned)((((sq * 4 + qq) ^ (sr & 7))) << 4);

    // ldmatrix thread bases
    const int rl = lane & 15, qsel = lane >> 4, sw7 = rl & 7;
    const unsigned thA = (unsigned)((wm * 64 + rl) * 128);
    const unsigned thB = (unsigned)((wn * 32 + rl) * 128);

    float cst[4][4];
    #pragma unroll
    for (int mt = 0; mt < 4; ++mt)
        #pragma unroll
        for (int e = 0; e < 4; ++e) cst[mt][e] = 0.f;

    #define LOADCHUNK(c, s) do {                                              \
        unsigned _db = sdst + (unsigned)((s) * 16384);                         \
        const char* _a0 = pA0 + (c) * 128;                                     \
        _Pragma("unroll")                                                      \
        for (int qq = 0; qq < 4; ++qq)                                         \
            cpa16(_db + swo[qq], _a0 + qq * 16);                               \
        asm volatile("cp.async.commit_group;" ::: "memory");                   \
    } while (0)

    for (int t = 0; t < 560; ++t) {
        // ---- step input ----
        float xtv[4][2];
        if (t < 512) {
            #pragma unroll
            for (int mt = 0; mt < 4; ++mt)
                #pragma unroll
                for (int hh = 0; hh < 2; ++hh)
                    xtv[mt][hh] = g_xT[t * 1024 + bth[mt][hh]];
        } else {
            int p = t - 512;
            #pragma unroll
            for (int mt = 0; mt < 4; ++mt)
                #pragma unroll
                for (int hh = 0; hh < 2; ++hh) {
                    xtv[mt][hh] = g_xdec[p * 1024 + bth[mt][hh]] + bfc;
                    if (j == 0 && wn == 0 && ql == 0)
                        dout[bth[mt][hh] * 48 + p] = xtv[mt][hh];
                }
            if (t == 559) break;
        }

        float D[4][4][4];
        #pragma unroll
        for (int mt = 0; mt < 4; ++mt)
            #pragma unroll
            for (int nt = 0; nt < 4; ++nt)
                #pragma unroll
                for (int e = 0; e < 4; ++e) D[mt][nt][e] = 0.f;

        // ---- GEMM: 8 double-buffered A-k64 chunks, single fp16 pass ----
        LOADCHUNK(0, 0);
        for (int c = 0; c < 8; ++c) {
            if (c < 7) {
                LOADCHUNK(c + 1, (c + 1) & 1);
                asm volatile("cp.async.wait_group 1;" ::: "memory");
            } else {
                asm volatile("cp.async.wait_group 0;" ::: "memory");
            }
            __syncthreads();
            const unsigned stA = sa + OFF_STA + (unsigned)((c & 1) * 16384);
            const unsigned stB = sa + (unsigned)(c * 16384);
            #pragma unroll
            for (int k16 = 0; k16 < 4; ++k16) {
                unsigned swz = (unsigned)((((k16 * 2 + qsel) ^ sw7)) << 4);
                uint32_t Bf[4][2];
                #pragma unroll
                for (int nb = 0; nb < 2; ++nb) {
                    uint32_t r0, r1, r2, r3;
                    ldmx4(r0, r1, r2, r3, stB + thB + nb * 2048 + swz);
                    Bf[2 * nb][0] = r0; Bf[2 * nb][1] = r2;
                    Bf[2 * nb + 1][0] = r1; Bf[2 * nb + 1][1] = r3;
                }
                #pragma unroll
                for (int mt = 0; mt < 4; ++mt) {
                    uint32_t a[4];
                    ldmx4(a[0], a[1], a[2], a[3], stA + thA + mt * 2048 + swz);
                    #pragma unroll
                    for (int nt = 0; nt < 4; ++nt)
                        mma16816(D[mt][nt], a, Bf[nt][0], Bf[nt][1]);
                }
            }
            __syncthreads();
        }

        // ---- epilogue: gates, c/h update, h store, fc ----
        #pragma unroll
        for (int mt = 0; mt < 4; ++mt) {
            #pragma unroll
            for (int hh = 0; hh < 2; ++hh) {
                float xt = xtv[mt][hh];
                float hv2[2];
                #pragma unroll
                for (int d = 0; d < 2; ++d) {
                    int e = hh * 2 + d;
                    float gi = D[mt][0][e] + bs[0][d] + xt * ws[0][d];
                    float gf = D[mt][1][e] + bs[1][d] + xt * ws[1][d];
                    float gg = D[mt][2][e] + bs[2][d] + xt * ws[2][d];
                    float go = D[mt][3][e] + bs[3][d] + xt * ws[3][d];
                    float c2 = sigm(gf) * cst[mt][e] + sigm(gi) * tanhx(gg);
                    cst[mt][e] = c2;
                    hv2[d] = sigm(go) * tanhx(c2);
                }
                __half h0 = __float2half_rn(hv2[0]);
                __half h1 = __float2half_rn(hv2[1]);
                uint32_t hiu = (uint32_t)__half_as_ushort(h0) |
                               ((uint32_t)__half_as_ushort(h1) << 16);
                size_t off = (size_t)bth[mt][hh] * 1024 + (size_t)kpos * 2;
                *(uint32_t*)((char*)g_hpack + off) = hiu;

                if (t >= 511 && t < 559) {
                    float pa = hv2[0] * wfc_r[0] + hv2[1] * wfc_r[1];
                    pa += __shfl_xor_sync(0xFFFFFFFFu, pa, 1);
                    pa += __shfl_xor_sync(0xFFFFFFFFu, pa, 2);
                    if (ql == 0)
                        atomicAdd(&g_xdec[(t - 511) * 1024 + bth[mt][hh]], pa);
                }
            }
        }

        grid_bar();
    }
    #undef LOADCHUNK
}

extern "C" void kernel_launch(void* const* d_in, const int* in_sizes, int n_in,
                              void* d_out, int out_size) {
    (void)in_sizes; (void)n_in; (void)out_size;
    cudaFuncSetAttribute(lstm_mma, cudaFuncAttributeMaxDynamicSharedMemorySize,
                         SMEM_MAIN);
    prep_k<<<2048, 256>>>((const float*)d_in[0]);
    pack_w<<<4096, 256>>>((const float*)d_in[2]);
    lstm_mma<<<NCTA, 256, SMEM_MAIN>>>(
        (const float*)d_in[1],   // w_ih
        (const float*)d_in[3],   // b_ih
        (const float*)d_in[4],   // b_hh
        (const float*)d_in[5],   // w_fc
        (const float*)d_in[6],   // b_fc
        (float*)d_out);
}

// round 9
// speedup vs baseline: 4.6769x; 1.0508x over previous
#include <cuda_runtime.h>
#include <cuda_fp16.h>
#include <cstdint>

#define NCTA 128
#define OFF_STA 131072                 // after 128KB resident w
#define SMEM_MAIN (131072 + 3 * 16384) // 180224

// ---------------- device scratch ----------------
__device__ __align__(128) unsigned char g_hpack[1048576]; // [b1024][k512] fp16 h
__device__ __align__(128) unsigned char g_wpack[2097152]; // [n2048 perm][k512] fp16 w
__device__ float g_xT[512 * 1024];
__device__ float g_xdec[48 * 1024];
__device__ unsigned g_cnt;
__device__ volatile unsigned g_gen;

__device__ __forceinline__ void grid_bar() {
    __syncthreads();
    if (threadIdx.x == 0) {
        __threadfence();
        unsigned gen = g_gen;
        unsigned t = atomicAdd(&g_cnt, 1u);
        if (t == NCTA - 1) { g_cnt = 0; __threadfence(); g_gen = gen + 1; }
        else { while (g_gen == gen) { __nanosleep(64); } }
        __threadfence();
    }
    __syncthreads();
}

__device__ __forceinline__ float tanha(float x) {
    float r;
    asm("tanh.approx.f32 %0, %1;" : "=f"(r) : "f"(x));
    return r;
}
__device__ __forceinline__ float sigm(float x) {
    return fmaf(tanha(0.5f * x), 0.5f, 0.5f);
}
__device__ __forceinline__ void cpa16(unsigned dst, const void* src) {
    asm volatile("cp.async.cg.shared.global [%0], [%1], 16;" :: "r"(dst), "l"(src));
}
__device__ __forceinline__ void ldmx4(uint32_t& r0, uint32_t& r1, uint32_t& r2,
                                      uint32_t& r3, unsigned a) {
    asm volatile("ldmatrix.sync.aligned.m8n8.x4.shared.b16 {%0,%1,%2,%3}, [%4];"
        : "=r"(r0), "=r"(r1), "=r"(r2), "=r"(r3) : "r"(a));
}
__device__ __forceinline__ void mma16816(float* d, const uint32_t* a,
                                         uint32_t b0, uint32_t b1) {
    asm volatile("mma.sync.aligned.m16n8k16.row.col.f32.f16.f16.f32 "
        "{%0,%1,%2,%3}, {%4,%5,%6,%7}, {%8,%9}, {%0,%1,%2,%3};"
        : "+f"(d[0]), "+f"(d[1]), "+f"(d[2]), "+f"(d[3])
        : "r"(a[0]), "r"(a[1]), "r"(a[2]), "r"(a[3]), "r"(b0), "r"(b1));
}

// ---------------- prologue kernels ----------------
extern "C" __global__ void prep_k(const float* __restrict__ x) {
    int n = blockIdx.x * 256 + threadIdx.x;          // 0..524287
    int b = n >> 9, t = n & 511;
    g_xT[t * 1024 + b] = x[n];                       // x[b][t][0]
    if (n < 262144) ((uint32_t*)g_hpack)[n] = 0u;    // zero h plane (1MB)
    if (n < 48 * 1024) g_xdec[n] = 0.f;
}

extern "C" __global__ void pack_w(const float* __restrict__ w_hh) {
    int n = blockIdx.x * 256 + threadIdx.x;          // 0..1048575
    int k = n & 511, ng = n >> 9;
    int j = ng >> 7, nl = ng & 127;
    int wn = nl >> 5, gate = (nl >> 3) & 3, ul = nl & 7;
    int row = gate * 512 + j * 32 + wn * 8 + ul;
    ((__half*)g_wpack)[ng * 512 + k] = __float2half_rn(w_hh[row * 512 + k]);
}

// ---------------- main persistent kernel ----------------
extern "C" __global__ void __launch_bounds__(256, 1)
lstm_mma(const float* __restrict__ w_ih, const float* __restrict__ b_ih,
         const float* __restrict__ b_hh, const float* __restrict__ w_fc,
         const float* __restrict__ b_fc, float* __restrict__ dout)
{
    extern __shared__ __align__(1024) char smem[];
    const unsigned sa = (unsigned)__cvta_generic_to_shared(smem);

    const int tid = threadIdx.x;
    const int lane = tid & 31, w = tid >> 5;
    const int wm = w >> 2, wn = w & 3;
    const int ql = lane & 3, qr = lane >> 2;
    const int i = blockIdx.x & 7, j = blockIdx.x >> 3;

    // per-thread constants: bias, w_ih, w_fc for its 2 units x 4 gates
    float bs[4][2], ws[4][2], wfc_r[2];
    #pragma unroll
    for (int d = 0; d < 2; ++d) {
        int u = j * 32 + wn * 8 + 2 * ql + d;
        wfc_r[d] = w_fc[u];
        #pragma unroll
        for (int g = 0; g < 4; ++g) {
            int row = g * 512 + u;
            bs[g][d] = b_ih[row] + b_hh[row];
            ws[g][d] = w_ih[row];
        }
    }
    const float bfc = b_fc[0];
    int bth[4][2];
    #pragma unroll
    for (int mt = 0; mt < 4; ++mt)
        #pragma unroll
        for (int hh = 0; hh < 2; ++hh)
            bth[mt][hh] = i * 128 + wm * 64 + mt * 16 + qr + 8 * hh;
    const int kpos = j * 32 + wn * 8 + 2 * ql;   // this thread's k-slot in h_pack

    // ---- resident w: 8 panels of [128 rows][64 k] fp16, SW128 swizzled ----
    for (int idx = tid; idx < 8192; idx += 256) {
        int c = idx >> 10, r = (idx >> 3) & 127, q = idx & 7;
        unsigned dst = sa + (unsigned)(c * 16384 + r * 128 + ((q ^ (r & 7)) * 16));
        const char* src = (const char*)g_wpack +
            ((size_t)(j * 128 + r)) * 1024 + c * 128 + q * 16;
        cpa16(dst, src);
    }
    asm volatile("cp.async.commit_group;\n\tcp.async.wait_group 0;" ::: "memory");
    __syncthreads();

    // staging (cp.async) parameters for A (h fp16), 16KB per chunk, 3-slot ring
    const int sr = tid >> 1, sq = tid & 1;
    const char* pA0 = (const char*)g_hpack + (size_t)(i * 128 + sr) * 1024 + sq * 64;
    const unsigned sdst = sa + OFF_STA + (unsigned)(sr * 128);
    unsigned swo[4];
    #pragma unroll
    for (int qq = 0; qq < 4; ++qq)
        swo[qq] = (unsigned)((((sq * 4 + qq) ^ (sr & 7))) << 4);

    // ldmatrix thread bases
    const int rl = lane & 15, qsel = lane >> 4, sw7 = rl & 7;
    const unsigned thA = (unsigned)((wm * 64 + rl) * 128);
    const unsigned thB = (unsigned)((wn * 32 + rl) * 128);

    float cst[4][4];
    #pragma unroll
    for (int mt = 0; mt < 4; ++mt)
        #pragma unroll
        for (int e = 0; e < 4; ++e) cst[mt][e] = 0.f;

    #define LOADCHUNK(c, s) do {                                              \
        unsigned _db = sdst + (unsigned)((s) * 16384);                         \
        const char* _a0 = pA0 + (c) * 128;                                     \
        _Pragma("unroll")                                                      \
        for (int qq = 0; qq < 4; ++qq)                                         \
            cpa16(_db + swo[qq], _a0 + qq * 16);                               \
        asm volatile("cp.async.commit_group;" ::: "memory");                   \
    } while (0)

    for (int t = 0; t < 560; ++t) {
        // stage chunks 0,1 first so they overlap the x loads below
        LOADCHUNK(0, 0);
        LOADCHUNK(1, 1);

        // ---- step input ----
        float xtv[4][2];
        bool last = false;
        if (t < 512) {
            #pragma unroll
            for (int mt = 0; mt < 4; ++mt)
                #pragma unroll
                for (int hh = 0; hh < 2; ++hh)
                    xtv[mt][hh] = g_xT[t * 1024 + bth[mt][hh]];
        } else {
            int p = t - 512;
            #pragma unroll
            for (int mt = 0; mt < 4; ++mt)
                #pragma unroll
                for (int hh = 0; hh < 2; ++hh) {
                    xtv[mt][hh] = g_xdec[p * 1024 + bth[mt][hh]] + bfc;
                    if (j == 0 && wn == 0 && ql == 0)
                        dout[bth[mt][hh] * 48 + p] = xtv[mt][hh];
                }
            last = (t == 559);
        }
        if (last) break;

        float D[4][4][4];
        #pragma unroll
        for (int mt = 0; mt < 4; ++mt)
            #pragma unroll
            for (int nt = 0; nt < 4; ++nt)
                #pragma unroll
                for (int e = 0; e < 4; ++e) D[mt][nt][e] = 0.f;

        // ---- GEMM: 8 chunks, 3-slot ring, one sync per chunk ----
        #pragma unroll 1
        for (int c = 0; c < 8; ++c) {
            if (c < 7)
                asm volatile("cp.async.wait_group 1;" ::: "memory");
            else
                asm volatile("cp.async.wait_group 0;" ::: "memory");
            __syncthreads();
            if (c + 2 < 8) {
                int s2 = c + 2; s2 = (s2 >= 3) ? (s2 >= 6 ? s2 - 6 : s2 - 3) : s2;
                LOADCHUNK(c + 2, s2);
            }
            int sc = (c >= 3) ? (c >= 6 ? c - 6 : c - 3) : c;
            const unsigned stA = sa + OFF_STA + (unsigned)(sc * 16384);
            const unsigned stB = sa + (unsigned)(c * 16384);
            #pragma unroll
            for (int k16 = 0; k16 < 4; ++k16) {
                unsigned swz = (unsigned)((((k16 * 2 + qsel) ^ sw7)) << 4);
                uint32_t Bf[4][2];
                #pragma unroll
                for (int nb = 0; nb < 2; ++nb) {
                    uint32_t r0, r1, r2, r3;
                    ldmx4(r0, r1, r2, r3, stB + thB + nb * 2048 + swz);
                    Bf[2 * nb][0] = r0; Bf[2 * nb][1] = r2;
                    Bf[2 * nb + 1][0] = r1; Bf[2 * nb + 1][1] = r3;
                }
                #pragma unroll
                for (int mt = 0; mt < 4; ++mt) {
                    uint32_t a[4];
                    ldmx4(a[0], a[1], a[2], a[3], stA + thA + mt * 2048 + swz);
                    #pragma unroll
                    for (int nt = 0; nt < 4; ++nt)
                        mma16816(D[mt][nt], a, Bf[nt][0], Bf[nt][1]);
                }
            }
        }

        // ---- epilogue: gates, c/h update, h store, fc ----
        #pragma unroll
        for (int mt = 0; mt < 4; ++mt) {
            #pragma unroll
            for (int hh = 0; hh < 2; ++hh) {
                float xt = xtv[mt][hh];
                float hv2[2];
                #pragma unroll
                for (int d = 0; d < 2; ++d) {
                    int e = hh * 2 + d;
                    float gi = D[mt][0][e] + bs[0][d] + xt * ws[0][d];
                    float gf = D[mt][1][e] + bs[1][d] + xt * ws[1][d];
                    float gg = D[mt][2][e] + bs[2][d] + xt * ws[2][d];
                    float go = D[mt][3][e] + bs[3][d] + xt * ws[3][d];
                    float c2 = sigm(gf) * cst[mt][e] + sigm(gi) * tanha(gg);
                    cst[mt][e] = c2;
                    hv2[d] = sigm(go) * tanha(c2);
                }
                __half h0 = __float2half_rn(hv2[0]);
                __half h1 = __float2half_rn(hv2[1]);
                uint32_t hiu = (uint32_t)__half_as_ushort(h0) |
                               ((uint32_t)__half_as_ushort(h1) << 16);
                size_t off = (size_t)bth[mt][hh] * 1024 + (size_t)kpos * 2;
                *(uint32_t*)((char*)g_hpack + off) = hiu;

                if (t >= 511) {
                    float pa = hv2[0] * wfc_r[0] + hv2[1] * wfc_r[1];
                    pa += __shfl_xor_sync(0xFFFFFFFFu, pa, 1);
                    pa += __shfl_xor_sync(0xFFFFFFFFu, pa, 2);
                    if (ql == 0)
                        atomicAdd(&g_xdec[(t - 511) * 1024 + bth[mt][hh]], pa);
                }
            }
        }

        grid_bar();
    }
    #undef LOADCHUNK
}

extern "C" void kernel_launch(void* const* d_in, const int* in_sizes, int n_in,
                              void* d_out, int out_size) {
    (void)in_sizes; (void)n_in; (void)out_size;
    cudaFuncSetAttribute(lstm_mma, cudaFuncAttributeMaxDynamicSharedMemorySize,
                         SMEM_MAIN);
    prep_k<<<2048, 256>>>((const float*)d_in[0]);
    pack_w<<<4096, 256>>>((const float*)d_in[2]);
    lstm_mma<<<NCTA, 256, SMEM_MAIN>>>(
        (const float*)d_in[1],   // w_ih
        (const float*)d_in[3],   // b_ih
        (const float*)d_in[4],   // b_hh
        (const float*)d_in[5],   // w_fc
        (const float*)d_in[6],   // b_fc
        (float*)d_out);
}

// round 10
// speedup vs baseline: 5.2275x; 1.1177x over previous
#include <cuda_runtime.h>
#include <cuda_fp16.h>
#include <cstdint>

#define NCTA 128
#define OFF_STA 131072                 // after 128KB resident w
#define SMEM_MAIN (131072 + 3 * 16384) // 180224

// ---------------- device scratch ----------------
__device__ __align__(128) unsigned char g_hpack[1048576]; // [b1024][k512] fp16 h
__device__ __align__(128) unsigned char g_wpack[2097152]; // [n2048 perm][k512] fp16 w
__device__ float g_xT[512 * 1024];
__device__ float g_xdec[48 * 1024];
__device__ __align__(128) unsigned g_cnt8[256];   // 8 group counters, 128B apart

__device__ __forceinline__ float tanha(float x) {
    float r;
    asm("tanh.approx.f32 %0, %1;" : "=f"(r) : "f"(x));
    return r;
}
__device__ __forceinline__ float sigm(float x) {
    return fmaf(tanha(0.5f * x), 0.5f, 0.5f);
}
__device__ __forceinline__ void cpa16(unsigned dst, const void* src) {
    asm volatile("cp.async.cg.shared.global [%0], [%1], 16;" :: "r"(dst), "l"(src));
}
__device__ __forceinline__ void ldmx4(uint32_t& r0, uint32_t& r1, uint32_t& r2,
                                      uint32_t& r3, unsigned a) {
    asm volatile("ldmatrix.sync.aligned.m8n8.x4.shared.b16 {%0,%1,%2,%3}, [%4];"
        : "=r"(r0), "=r"(r1), "=r"(r2), "=r"(r3) : "r"(a));
}
__device__ __forceinline__ void mma16816(float* d, const uint32_t* a,
                                         uint32_t b0, uint32_t b1) {
    asm volatile("mma.sync.aligned.m16n8k16.row.col.f32.f16.f16.f32 "
        "{%0,%1,%2,%3}, {%4,%5,%6,%7}, {%8,%9}, {%0,%1,%2,%3};"
        : "+f"(d[0]), "+f"(d[1]), "+f"(d[2]), "+f"(d[3])
        : "r"(a[0]), "r"(a[1]), "r"(a[2]), "r"(a[3]), "r"(b0), "r"(b1));
}

// ---------------- prologue kernels ----------------
extern "C" __global__ void prep_k(const float* __restrict__ x) {
    int n = blockIdx.x * 256 + threadIdx.x;          // 0..524287
    int b = n >> 9, t = n & 511;
    g_xT[t * 1024 + b] = x[n];                       // x[b][t][0]
    if (n < 262144) ((uint32_t*)g_hpack)[n] = 0u;    // zero h plane (1MB)
    if (n < 48 * 1024) g_xdec[n] = 0.f;
    if (n < 256) g_cnt8[n] = 0u;                     // reset group barriers
}

extern "C" __global__ void pack_w(const float* __restrict__ w_hh) {
    int n = blockIdx.x * 256 + threadIdx.x;          // 0..1048575
    int k = n & 511, ng = n >> 9;
    int j = ng >> 7, nl = ng & 127;
    int wn = nl >> 5, gate = (nl >> 3) & 3, ul = nl & 7;
    int row = gate * 512 + j * 32 + wn * 8 + ul;
    ((__half*)g_wpack)[ng * 512 + k] = __float2half_rn(w_hh[row * 512 + k]);
}

// ---------------- main persistent kernel ----------------
extern "C" __global__ void __launch_bounds__(256, 1)
lstm_mma(const float* __restrict__ w_ih, const float* __restrict__ b_ih,
         const float* __restrict__ b_hh, const float* __restrict__ w_fc,
         const float* __restrict__ b_fc, float* __restrict__ dout)
{
    extern __shared__ __align__(1024) char smem[];
    const unsigned sa = (unsigned)__cvta_generic_to_shared(smem);

    const int tid = threadIdx.x;
    const int lane = tid & 31, w = tid >> 5;
    const int wm = w >> 2, wn = w & 3;
    const int ql = lane & 3, qr = lane >> 2;
    const int i = blockIdx.x & 7, j = blockIdx.x >> 3;
    unsigned* const cptr = g_cnt8 + (i << 5);   // this group's barrier counter

    // per-thread constants: bias, w_ih, w_fc for its 2 units x 4 gates
    float bs[4][2], ws[4][2], wfc_r[2];
    #pragma unroll
    for (int d = 0; d < 2; ++d) {
        int u = j * 32 + wn * 8 + 2 * ql + d;
        wfc_r[d] = w_fc[u];
        #pragma unroll
        for (int g = 0; g < 4; ++g) {
            int row = g * 512 + u;
            bs[g][d] = b_ih[row] + b_hh[row];
            ws[g][d] = w_ih[row];
        }
    }
    const float bfc = b_fc[0];
    int bth[4][2];
    #pragma unroll
    for (int mt = 0; mt < 4; ++mt)
        #pragma unroll
        for (int hh = 0; hh < 2; ++hh)
            bth[mt][hh] = i * 128 + wm * 64 + mt * 16 + qr + 8 * hh;
    const int kpos = j * 32 + wn * 8 + 2 * ql;   // this thread's k-slot in h_pack

    // ---- resident w: 8 panels of [128 rows][64 k] fp16, SW128 swizzled ----
    for (int idx = tid; idx < 8192; idx += 256) {
        int c = idx >> 10, r = (idx >> 3) & 127, q = idx & 7;
        unsigned dst = sa + (unsigned)(c * 16384 + r * 128 + ((q ^ (r & 7)) * 16));
        const char* src = (const char*)g_wpack +
            ((size_t)(j * 128 + r)) * 1024 + c * 128 + q * 16;
        cpa16(dst, src);
    }
    asm volatile("cp.async.commit_group;\n\tcp.async.wait_group 0;" ::: "memory");
    __syncthreads();

    // staging (cp.async) parameters for A (h fp16), 16KB per chunk, 3-slot ring
    const int sr = tid >> 1, sq = tid & 1;
    const char* pA0 = (const char*)g_hpack + (size_t)(i * 128 + sr) * 1024 + sq * 64;
    const unsigned sdst = sa + OFF_STA + (unsigned)(sr * 128);
    unsigned swo[4];
    #pragma unroll
    for (int qq = 0; qq < 4; ++qq)
        swo[qq] = (unsigned)((((sq * 4 + qq) ^ (sr & 7))) << 4);

    // ldmatrix thread bases
    const int rl = lane & 15, qsel = lane >> 4, sw7 = rl & 7;
    const unsigned thA = (unsigned)((wm * 64 + rl) * 128);
    const unsigned thB = (unsigned)((wn * 32 + rl) * 128);

    float cst[4][4];
    #pragma unroll
    for (int mt = 0; mt < 4; ++mt)
        #pragma unroll
        for (int e = 0; e < 4; ++e) cst[mt][e] = 0.f;

    #define LOADCHUNK(c, s) do {                                              \
        unsigned _db = sdst + (unsigned)((s) * 16384);                         \
        const char* _a0 = pA0 + (c) * 128;                                     \
        _Pragma("unroll")                                                      \
        for (int qq = 0; qq < 4; ++qq)                                         \
            cpa16(_db + swo[qq], _a0 + qq * 16);                               \
        asm volatile("cp.async.commit_group;" ::: "memory");                   \
    } while (0)

    for (int t = 0; t < 560; ++t) {
        // ---- group barrier wait: h(t) and xdec(t) produced by group i ----
        if (t > 0) {
            if (tid == 0) {
                unsigned tgt = (unsigned)(t << 4);   // 16*t arrivals
                unsigned v;
                do {
                    asm volatile("ld.acquire.gpu.global.u32 %0, [%1];"
                                 : "=r"(v) : "l"(cptr) : "memory");
                    if (v < tgt) __nanosleep(32);
                } while (v < tgt);
            }
            __syncthreads();
        }

        // stage chunks 0,1 so they overlap the x loads below
        LOADCHUNK(0, 0);
        LOADCHUNK(1, 1);

        // ---- step input ----
        float xtv[4][2];
        if (t < 512) {
            #pragma unroll
            for (int mt = 0; mt < 4; ++mt)
                #pragma unroll
                for (int hh = 0; hh < 2; ++hh)
                    xtv[mt][hh] = g_xT[t * 1024 + bth[mt][hh]];
        } else {
            int p = t - 512;
            #pragma unroll
            for (int mt = 0; mt < 4; ++mt)
                #pragma unroll
                for (int hh = 0; hh < 2; ++hh) {
                    xtv[mt][hh] = g_xdec[p * 1024 + bth[mt][hh]] + bfc;
                    if (j == 0 && wn == 0 && ql == 0)
                        dout[bth[mt][hh] * 48 + p] = xtv[mt][hh];
                }
            if (t == 559) break;
        }

        float D[4][4][4];
        #pragma unroll
        for (int mt = 0; mt < 4; ++mt)
            #pragma unroll
            for (int nt = 0; nt < 4; ++nt)
                #pragma unroll
                for (int e = 0; e < 4; ++e) D[mt][nt][e] = 0.f;

        // ---- GEMM: 8 chunks, 3-slot ring, one sync per chunk ----
        #pragma unroll 1
        for (int c = 0; c < 8; ++c) {
            if (c < 7)
                asm volatile("cp.async.wait_group 1;" ::: "memory");
            else
                asm volatile("cp.async.wait_group 0;" ::: "memory");
            __syncthreads();
            if (c + 2 < 8) {
                int s2 = c + 2; s2 = (s2 >= 3) ? (s2 >= 6 ? s2 - 6 : s2 - 3) : s2;
                LOADCHUNK(c + 2, s2);
            }
            int sc = (c >= 3) ? (c >= 6 ? c - 6 : c - 3) : c;
            const unsigned stA = sa + OFF_STA + (unsigned)(sc * 16384);
            const unsigned stB = sa + (unsigned)(c * 16384);
            #pragma unroll
            for (int k16 = 0; k16 < 4; ++k16) {
                unsigned swz = (unsigned)((((k16 * 2 + qsel) ^ sw7)) << 4);
                uint32_t Bf[4][2];
                #pragma unroll
                for (int nb = 0; nb < 2; ++nb) {
                    uint32_t r0, r1, r2, r3;
                    ldmx4(r0, r1, r2, r3, stB + thB + nb * 2048 + swz);
                    Bf[2 * nb][0] = r0; Bf[2 * nb][1] = r2;
                    Bf[2 * nb + 1][0] = r1; Bf[2 * nb + 1][1] = r3;
                }
                #pragma unroll
                for (int mt = 0; mt < 4; ++mt) {
                    uint32_t a[4];
                    ldmx4(a[0], a[1], a[2], a[3], stA + thA + mt * 2048 + swz);
                    #pragma unroll
                    for (int nt = 0; nt < 4; ++nt)
                        mma16816(D[mt][nt], a, Bf[nt][0], Bf[nt][1]);
                }
            }
        }

        // ---- epilogue: gates, c/h update, h store, fc ----
        #pragma unroll
        for (int mt = 0; mt < 4; ++mt) {
            #pragma unroll
            for (int hh = 0; hh < 2; ++hh) {
                float xt = xtv[mt][hh];
                float hv2[2];
                #pragma unroll
                for (int d = 0; d < 2; ++d) {
                    int e = hh * 2 + d;
                    float gi = D[mt][0][e] + bs[0][d] + xt * ws[0][d];
                    float gf = D[mt][1][e] + bs[1][d] + xt * ws[1][d];
                    float gg = D[mt][2][e] + bs[2][d] + xt * ws[2][d];
                    float go = D[mt][3][e] + bs[3][d] + xt * ws[3][d];
                    float c2 = sigm(gf) * cst[mt][e] + sigm(gi) * tanha(gg);
                    cst[mt][e] = c2;
                    hv2[d] = sigm(go) * tanha(c2);
                }
                __half h0 = __float2half_rn(hv2[0]);
                __half h1 = __float2half_rn(hv2[1]);
                uint32_t hiu = (uint32_t)__half_as_ushort(h0) |
                               ((uint32_t)__half_as_ushort(h1) << 16);
                size_t off = (size_t)bth[mt][hh] * 1024 + (size_t)kpos * 2;
                *(uint32_t*)((char*)g_hpack + off) = hiu;

                if (t >= 511) {
                    float pa = hv2[0] * wfc_r[0] + hv2[1] * wfc_r[1];
                    pa += __shfl_xor_sync(0xFFFFFFFFu, pa, 1);
                    pa += __shfl_xor_sync(0xFFFFFFFFu, pa, 2);
                    if (ql == 0)
                        atomicAdd(&g_xdec[(t - 511) * 1024 + bth[mt][hh]], pa);
                }
            }
        }

        // ---- group barrier arrive (release: orders h stores + xdec adds) ----
        __syncthreads();
        if (tid == 0)
            asm volatile("red.release.gpu.global.add.u32 [%0], 1;"
                         :: "l"(cptr) : "memory");
    }
    #undef LOADCHUNK
}

extern "C" void kernel_launch(void* const* d_in, const int* in_sizes, int n_in,
                              void* d_out, int out_size) {
    (void)in_sizes; (void)n_in; (void)out_size;
    cudaFuncSetAttribute(lstm_mma, cudaFuncAttributeMaxDynamicSharedMemorySize,
                         SMEM_MAIN);
    prep_k<<<2048, 256>>>((const float*)d_in[0]);
    pack_w<<<4096, 256>>>((const float*)d_in[2]);
    lstm_mma<<<NCTA, 256, SMEM_MAIN>>>(
        (const float*)d_in[1],   // w_ih
        (const float*)d_in[3],   // b_ih
        (const float*)d_in[4],   // b_hh
        (const float*)d_in[5],   // w_fc
        (const float*)d_in[6],   // b_fc
        (float*)d_out);
}